// round 12
// baseline (speedup 1.0000x reference)
#include <cuda_runtime.h>
#include <cuda_fp16.h>
#include <mma.h>
#include <stdint.h>
#include <math.h>

using namespace nvcuda;

#define NT 1024
#define HD 128
#define ED 64
#define SC 32
#define PP 32
#define B1D 512
#define B2D 1024
#define M1D 1024
#define TS 12
#define KM1 (HD + B2D)   // 1152
#define BN_INV_F 0.9999950000374997f

// ---------------- device state / scratch ----------------
static __device__ float g_h[NT * HD];
static __device__ float g_c[NT * HD];
static __device__ float g_h2[NT * HD];
static __device__ float g_lp[NT * 2];
static __device__ float g_din[NT * ED];
static __device__ float g_hpre[NT * B1D];
static __device__ float g_gates[NT * 4 * HD];
static __device__ float g_hp[4 * NT * HD];     // m2 split-K partials
// folded scalar weights
static __device__ float g_A[B1D], g_B[B1D], g_bias1[B1D];
static __device__ float g_Wb[B1D * HD];
static __device__ float g_bias2[B2D], g_bm1[M1D], g_bm2[HD];
static __device__ float g_LW[4 * HD * 192], g_Lb[4 * HD];
// pre-tiled fp16 weights: [nb][chunk64][128r x 64k] tiles (8192 halfs)
static __device__ __half g_W2th[8 * 8 * 8192];
static __device__ __half g_M1th[8 * 18 * 8192];
static __device__ __half g_M2th[16 * 8192];
// activation tiles, fp16, [group][chunk64][128x64]
static __device__ __half g_x1h[256 * 8 * 8192];   // pool A
static __device__ __half g_mAh[8 * 18 * 8192];    // m1 A
static __device__ __half g_mBh[8 * 16 * 8192];    // m2 A

// ---------------- helpers ----------------
__device__ __forceinline__ uint32_t pack2hf(float v0, float v1) {
    __half2 h = __floats2half2_rn(v0, v1);
    return *(uint32_t*)&h;
}
__device__ __forceinline__ uint32_t smem_u32(const void* p) {
    uint32_t a;
    asm("{ .reg .u64 t; cvta.to.shared.u64 t, %1; cvt.u32.u64 %0, t; }" : "=r"(a) : "l"(p));
    return a;
}
__device__ __forceinline__ void cpa(uint32_t dsmem, const void* gsrc) {
    asm volatile("cp.async.cg.shared.global [%0], [%1], 16;" :: "r"(dsmem), "l"(gsrc) : "memory");
}
#define CPA_COMMIT() asm volatile("cp.async.commit_group;" ::: "memory")
#define CPA_WAIT2()  asm volatile("cp.async.wait_group 2;" ::: "memory")
#define CPA_WAIT1()  asm volatile("cp.async.wait_group 1;" ::: "memory")
#define CPA_WAIT0()  asm volatile("cp.async.wait_group 0;" ::: "memory")

// ---------------- prep kernels (once per launch) ----------------
__global__ void init_state(const float* __restrict__ h0, const float* __restrict__ c0,
                           const float* __restrict__ last_pos, const float* __restrict__ last_pos_rel,
                           const float* __restrict__ embW, const float* __restrict__ embb) {
    int idx = blockIdx.x * blockDim.x + threadIdx.x;
    if (idx < NT * HD) { g_h[idx] = h0[idx]; g_c[idx] = c0[idx]; }
    if (idx < NT * 2) g_lp[idx] = last_pos[idx];
    if (idx < NT * ED) {
        int n = idx / ED, e = idx % ED;
        g_din[idx] = last_pos_rel[n * 2] * embW[e * 2] +
                     last_pos_rel[n * 2 + 1] * embW[e * 2 + 1] + embb[e];
    }
}

__global__ void fold_pp1(const float* __restrict__ pp1_W, const float* __restrict__ pp1_b,
                         const float* __restrict__ pp1_g, const float* __restrict__ pp1_be,
                         const float* __restrict__ sp_W, const float* __restrict__ sp_b) {
    int k = blockIdx.x * blockDim.x + threadIdx.x;
    if (k >= B1D) return;
    float s1 = BN_INV_F * pp1_g[k];
    const float* row = pp1_W + (size_t)k * (ED + HD);
    float sa = 0.f, sb = 0.f, sc = 0.f;
    for (int e = 0; e < ED; e++) {
        float w = row[e];
        sa += w * sp_W[e * 2]; sb += w * sp_W[e * 2 + 1]; sc += w * sp_b[e];
    }
    g_A[k] = sa * s1; g_B[k] = sb * s1;
    g_bias1[k] = (pp1_b[k] + sc) * s1 + pp1_be[k];
    for (int h = 0; h < HD; h++) g_Wb[k * HD + h] = row[ED + h] * s1;
}

__global__ void fold_LW(const float* __restrict__ Wih, const float* __restrict__ Whh,
                        const float* __restrict__ bih, const float* __restrict__ bhh) {
    for (int idx = blockIdx.x * blockDim.x + threadIdx.x; idx < 512 * 192; idx += gridDim.x * blockDim.x) {
        int r = idx / 192, cc = idx % 192;
        g_LW[idx] = (cc < 64) ? Wih[r * 64 + cc] : Whh[r * 128 + cc - 64];
        if (cc == 0) g_Lb[r] = bih[r] + bhh[r];
    }
}

// fp16 pre-tiled weights. WM=0: W2(K=512), 1: m1(K=1152), 2: m2(K=1024,R=128)
template <int WM>
__global__ void prep_wB(const float* __restrict__ W, const float* __restrict__ b,
                        const float* __restrict__ g, const float* __restrict__ be) {
    constexpr int K = (WM == 0) ? B1D : (WM == 1) ? KM1 : M1D;
    constexpr int ROWS = (WM == 2) ? HD : 1024;
    constexpr int KC = K / 64;
    __half* oh = (WM == 0) ? g_W2th : (WM == 1) ? g_M1th : g_M2th;
    float* bo = (WM == 0) ? g_bias2 : (WM == 1) ? g_bm1 : g_bm2;
    int total = ROWS * (K / 2);
    for (int p = blockIdx.x * blockDim.x + threadIdx.x; p < total; p += gridDim.x * blockDim.x) {
        int co = p / (K / 2), kp = p % (K / 2), k = kp * 2;
        int nb = co >> 7, r = co & 127, c = k >> 6;
        float s = BN_INV_F * g[co];
        float v0 = W[(size_t)co * K + k] * s, v1 = W[(size_t)co * K + k + 1] * s;
        size_t woff = (size_t)(nb * KC + c) * 4096 + r * 32 + (kp & 31);
        ((uint32_t*)oh)[woff] = pack2hf(v0, v1);
        if (kp == 0) bo[co] = b[co] * s + be[co];
    }
}

// ---------------- SIMT GEMM: MODE 0 hpre(K=128), MODE 2 gates(K=192) ----------------
template <int MODE, int FIRST>
__global__ __launch_bounds__(256) void tile_gemm() {
    constexpr int K = (MODE == 0) ? HD : 192;
    constexpr int LDC = (MODE == 0) ? B1D : 512;
    const float* Wp = (MODE == 0) ? g_Wb : g_LW;
    const float* bp = (MODE == 0) ? g_bias1 : g_Lb;
    float* outp = (MODE == 0) ? g_hpre : g_gates;
    int c0 = blockIdx.x * 128, grp = blockIdx.y, tid = threadIdx.x;
    int tx = tid & 31, ty = tid >> 5;
    __shared__ float a_s[32][64];
    __shared__ float w_s[64][129];
    int nbase = grp * 32;
    float acc[4][4] = {};
    for (int k0 = 0; k0 < K; k0 += 64) {
        __syncthreads();
        for (int idx = tid; idx < 32 * 64; idx += 256) {
            int j = idx >> 6, k = idx & 63, kk = k0 + k;
            float v;
            if (MODE == 0) v = g_h2[(nbase + j) * HD + kk];
            else if (kk < 64) v = g_din[(nbase + j) * ED + kk];
            else {
                int ped = nbase + j, cc = kk - 64;
                if (FIRST) v = g_h[ped * HD + cc];
                else {
                    float sum = g_hp[(size_t)ped * HD + cc]
                              + g_hp[(size_t)(NT + ped) * HD + cc]
                              + g_hp[(size_t)(2 * NT + ped) * HD + cc]
                              + g_hp[(size_t)(3 * NT + ped) * HD + cc];
                    v = fmaxf(sum + g_bm2[cc], 0.f);
                }
            }
            a_s[j][k] = v;
        }
        for (int idx = tid; idx < 128 * 64; idx += 256) {
            int c = idx >> 6, k = idx & 63;
            w_s[k][c] = Wp[(size_t)(c0 + c) * K + k0 + k];
        }
        __syncthreads();
#pragma unroll 4
        for (int k = 0; k < 64; k++) {
            float xr[4], wr[4];
#pragma unroll
            for (int jj = 0; jj < 4; jj++) xr[jj] = a_s[ty + jj * 8][k];
#pragma unroll
            for (int cc = 0; cc < 4; cc++) wr[cc] = w_s[k][tx + cc * 32];
#pragma unroll
            for (int jj = 0; jj < 4; jj++)
#pragma unroll
                for (int cc = 0; cc < 4; cc++) acc[jj][cc] = fmaf(xr[jj], wr[cc], acc[jj][cc]);
        }
    }
#pragma unroll
    for (int jj = 0; jj < 4; jj++) {
        int n = nbase + ty + jj * 8;
#pragma unroll
        for (int cc = 0; cc < 4; cc++) {
            int c = c0 + tx + cc * 32;
            outp[(size_t)n * LDC + c] = acc[jj][cc] + bp[c];
        }
    }
}

// ---------------- LSTM pointwise + h2 pack into m1 A-tiles ----------------
__global__ __launch_bounds__(128) void lstm_point(
    const float* __restrict__ posW, const float* __restrict__ posb,
    const float* __restrict__ embW, const float* __restrict__ embb,
    float* __restrict__ out_t) {
    int n = blockIdx.x, t = threadIdx.x;
    __shared__ float red0[HD], red1[HD], hs2[HD], rp[2];
    float gi = g_gates[n * 512 + 0 * HD + t];
    float gf = g_gates[n * 512 + 1 * HD + t];
    float gg = g_gates[n * 512 + 2 * HD + t];
    float go = g_gates[n * 512 + 3 * HD + t];
    float ig = 1.f / (1.f + expf(-gi));
    float fg = 1.f / (1.f + expf(-gf));
    float gv = tanhf(gg);
    float og = 1.f / (1.f + expf(-go));
    float c2 = fg * g_c[n * HD + t] + ig * gv;
    float h2 = og * tanhf(c2);
    g_c[n * HD + t] = c2;
    g_h2[n * HD + t] = h2;
    hs2[t] = h2;
    red0[t] = h2 * posW[t]; red1[t] = h2 * posW[HD + t];
    __syncthreads();
    for (int s = 64; s > 0; s >>= 1) {
        if (t < s) { red0[t] += red0[t + s]; red1[t] += red1[t + s]; }
        __syncthreads();
    }
    if (t < 2) {
        float v = ((t == 0) ? red0[0] : red1[0]) + posb[t];
        rp[t] = v;
        out_t[n * 2 + t] = v;
        g_lp[n * 2 + t] += v;
    }
    __syncthreads();
    if (t < ED) g_din[n * ED + t] = fmaf(rp[0], embW[t * 2], fmaf(rp[1], embW[t * 2 + 1], embb[t]));
    if (t < 64) {
        int mb = n >> 7, m = n & 127;
        int c = t >> 5;
        ((uint32_t*)g_mAh)[(size_t)(mb * 18 + c) * 4096 + m * 32 + (t & 31)] =
            pack2hf(hs2[2 * t], hs2[2 * t + 1]);
    }
}

// ---------------- build x1 fp16 tiles (once per step) ----------------
__global__ __launch_bounds__(256) void build_x1() {
    int c = blockIdx.x, ib = blockIdx.y, s = blockIdx.z;
    int tid = threadIdx.x;
    __shared__ float rxs[128], rys[128];
    if (tid < 128) {
        int i = ib * 4 + (tid >> 5), j = tid & 31;
        float dx = g_lp[(s * 32 + j) * 2]     - g_lp[(s * 32 + i) * 2];
        float dy = g_lp[(s * 32 + j) * 2 + 1] - g_lp[(s * 32 + i) * 2 + 1];
        float nrm = fmaxf(sqrtf(dx * dx + dy * dy), 1e-12f);
        rxs[tid] = dx / nrm; rys[tid] = dy / nrm;
    }
    __syncthreads();
    int grp = s * 8 + ib;
    uint32_t* oh = (uint32_t*)g_x1h + (size_t)(grp * 8 + c) * 4096;
    int kp = tid & 31, k = c * 64 + kp * 2;
    float2 ab0 = *(const float2*)(g_A + k);
    float2 bb0 = *(const float2*)(g_B + k);
#pragma unroll
    for (int q = 0; q < 16; q++) {
        int m = (tid >> 5) + q * 8;
        int pj = s * 32 + (m & 31);
        float rx = rxs[m], ry = rys[m];
        float2 hp = *(const float2*)(g_hpre + (size_t)pj * B1D + k);
        float v0 = fmaxf(hp.x + rx * ab0.x + ry * bb0.x, 0.f);
        float v1 = fmaxf(hp.y + rx * ab0.y + ry * bb0.y, 0.f);
        oh[m * 32 + kp] = pack2hf(v0, v1);
    }
}

// ---------------- wmma fp16 single-pass GEMM, 3-stage cp.async ring ----------------
// GM=0: pool, grid(8 nb, 128), GROUPS=2 (M=2x128), KC=16, warp tile 32x64
// GM=1: m1,   grid(8 nb, 16),  GROUPS=1, ROWS=64, KC=36, warp tile 32x32
// GM=2: m2,   grid(4 ksl, 8),  GROUPS=1, ROWS=128, KC=8, warp tile 32x64
template <int GM>
__global__ __launch_bounds__(256) void wmma_gemm() {
    constexpr int KC = (GM == 0) ? 16 : (GM == 1) ? 36 : 8;
    constexpr int GROUPS = (GM == 0) ? 2 : 1;
    constexpr int ROWS = (GM == 1) ? 64 : 128;
    constexpr int NF = (GM == 1) ? 2 : 4;
    constexpr int WC = (GM == 1) ? 4 : 2;
    constexpr int SA = ROWS * 80;
    constexpr int SS = GROUPS * SA + 10240;
    extern __shared__ __align__(16) char smraw[];
    uint32_t base = smem_u32(smraw);
    float* c_s = (float*)smraw;

    int tid = threadIdx.x, w = tid >> 5;
    int wr = w / WC, wc = w % WC;
    int nbX = blockIdx.x, grpY = blockIdx.y;

    const __half* Ah_g = (GM == 0) ? g_x1h : (GM == 1) ? g_mAh : g_mBh;
    const __half* Wh_g = (GM == 0) ? g_W2th : (GM == 1) ? g_M1th : g_M2th;

    auto stage = [&](int buf, int c) {
        int tile0 = 0, tile1 = 0, sub, roff = 0, wtile;
        if (GM == 0) {
            int ch = c >> 1; sub = c & 1;
            tile0 = (grpY * 2) * 8 + ch; tile1 = (grpY * 2 + 1) * 8 + ch;
            wtile = nbX * 8 + ch;
        } else if (GM == 1) {
            int ch = c >> 1; sub = c & 1;
            tile0 = (grpY >> 1) * 18 + ch; roff = (grpY & 1) * 64;
            wtile = nbX * 18 + ch;
        } else {
            int gch = nbX * 8 + c; sub = gch & 1;
            tile0 = grpY * 16 + (gch >> 1);
            wtile = gch >> 1;
        }
        uint32_t sb = base + buf * SS;
        for (int i = tid; i < GROUPS * ROWS * 4; i += 256) {
            int g = i / (ROWS * 4), r = (i >> 2) % ROWS, seg = i & 3;
            int tile = g ? tile1 : tile0;
            size_t so = (size_t)tile * 8192 + (roff + r) * 64 + sub * 32 + seg * 8;
            cpa(sb + g * SA + r * 80 + seg * 16, Ah_g + so);
        }
        for (int i = tid; i < 512; i += 256) {
            int r = i >> 2, seg = i & 3;
            size_t so = (size_t)wtile * 8192 + r * 64 + sub * 32 + seg * 8;
            cpa(sb + GROUPS * SA + r * 80 + seg * 16, Wh_g + so);
        }
        CPA_COMMIT();
    };

    wmma::fragment<wmma::accumulator, 16, 16, 16, float> acc[GROUPS][2][NF];
#pragma unroll
    for (int g = 0; g < GROUPS; g++)
#pragma unroll
        for (int mf = 0; mf < 2; mf++)
#pragma unroll
            for (int nf = 0; nf < NF; nf++) wmma::fill_fragment(acc[g][mf][nf], 0.f);

    stage(0, 0);
    if (KC > 1) stage(1, 1);
    for (int c = 0; c < KC; c++) {
        if (c + 2 < KC) { stage((c + 2) % 3, c + 2); CPA_WAIT2(); }
        else if (c + 1 < KC) { CPA_WAIT1(); }
        else { CPA_WAIT0(); }
        __syncthreads();
        const __half* sbuf = (const __half*)(smraw + (c % 3) * SS);
        const __half* whp = sbuf + (GROUPS * SA) / 2;
#pragma unroll
        for (int ks = 0; ks < 2; ks++) {
            wmma::fragment<wmma::matrix_a, 16, 16, 16, __half, wmma::row_major> af[GROUPS][2];
#pragma unroll
            for (int g = 0; g < GROUPS; g++)
#pragma unroll
                for (int mf = 0; mf < 2; mf++)
                    wmma::load_matrix_sync(af[g][mf],
                        sbuf + g * (SA / 2) + (wr * 32 + mf * 16) * 40 + ks * 16, 40);
#pragma unroll
            for (int nf = 0; nf < NF; nf++) {
                wmma::fragment<wmma::matrix_b, 16, 16, 16, __half, wmma::col_major> bh;
                int coff = (wc * NF * 16 + nf * 16) * 40 + ks * 16;
                wmma::load_matrix_sync(bh, whp + coff, 40);
#pragma unroll
                for (int g = 0; g < GROUPS; g++)
#pragma unroll
                    for (int mf = 0; mf < 2; mf++)
                        wmma::mma_sync(acc[g][mf][nf], af[g][mf], bh, acc[g][mf][nf]);
            }
        }
        __syncthreads();
    }

    for (int g = 0; g < GROUPS; g++) {
        __syncthreads();
#pragma unroll
        for (int mf = 0; mf < 2; mf++)
#pragma unroll
            for (int nf = 0; nf < NF; nf++)
                wmma::store_matrix_sync(c_s + (wr * 32 + mf * 16) * 136 + wc * NF * 16 + nf * 16,
                                        acc[g][mf][nf], 136, wmma::mem_row_major);
        __syncthreads();

        if (GM == 0) {
            int grp = grpY * 2 + g;
            int s = grp >> 3, ib = grp & 7;
            if (tid < 256) {
                int il = tid >> 6, kp0 = tid & 63;
                int cc0 = kp0 * 2;
                float m0 = c_s[(il * 32) * 136 + cc0];
                float m1v = c_s[(il * 32) * 136 + cc0 + 1];
#pragma unroll 8
                for (int r = 1; r < 32; r++) {
                    m0  = fmaxf(m0,  c_s[(il * 32 + r) * 136 + cc0]);
                    m1v = fmaxf(m1v, c_s[(il * 32 + r) * 136 + cc0 + 1]);
                }
                int col = nbX * 128 + cc0;
                float v0 = fmaxf(m0 + g_bias2[col], 0.f);
                float v1 = fmaxf(m1v + g_bias2[col + 1], 0.f);
                int ped = s * 32 + ib * 4 + il;
                int mb = ped >> 7, m = ped & 127;
                int cch = 2 + nbX * 2 + (kp0 >> 5);
                ((uint32_t*)g_mAh)[(size_t)(mb * 18 + cch) * 4096 + m * 32 + (kp0 & 31)] =
                    pack2hf(v0, v1);
            }
        } else if (GM == 1) {
            for (int p = tid; p < 4096; p += 256) {
                int r = p >> 6, kp = p & 63;
                int cc0 = kp * 2, col = nbX * 128 + cc0;
                float v0 = fmaxf(c_s[r * 136 + cc0]     + g_bm1[col], 0.f);
                float v1 = fmaxf(c_s[r * 136 + cc0 + 1] + g_bm1[col + 1], 0.f);
                int ped = grpY * 64 + r;
                int mb = ped >> 7, m = ped & 127;
                int cch = nbX * 2 + (kp >> 5);
                ((uint32_t*)g_mBh)[(size_t)(mb * 16 + cch) * 4096 + m * 32 + (kp & 31)] =
                    pack2hf(v0, v1);
            }
        } else {
            float* dst = g_hp + (size_t)nbX * NT * HD + (size_t)grpY * 128 * HD;
            for (int p = tid; p < 16384; p += 256) {
                int r = p >> 7, cc = p & 127;
                dst[r * HD + cc] = c_s[r * 136 + cc];
            }
        }
    }
}

// ---------------- host launch ----------------
extern "C" void kernel_launch(void* const* d_in, const int* in_sizes, int n_in,
                              void* d_out, int out_size) {
    const float* last_pos     = (const float*)d_in[0];
    const float* last_pos_rel = (const float*)d_in[1];
    const float* h0  = (const float*)d_in[2];
    const float* c0  = (const float*)d_in[3];
    const float* emb_W = (const float*)d_in[5];
    const float* emb_b = (const float*)d_in[6];
    const float* Wih = (const float*)d_in[7];
    const float* Whh = (const float*)d_in[8];
    const float* bih = (const float*)d_in[9];
    const float* bhh = (const float*)d_in[10];
    const float* pos_W = (const float*)d_in[11];
    const float* pos_b = (const float*)d_in[12];
    const float* sp_W = (const float*)d_in[13];
    const float* sp_b = (const float*)d_in[14];
    const float* pp1_W = (const float*)d_in[15];
    const float* pp1_b = (const float*)d_in[16];
    const float* pp1_g = (const float*)d_in[17];
    const float* pp1_be = (const float*)d_in[18];
    const float* pp2_W = (const float*)d_in[19];
    const float* pp2_b = (const float*)d_in[20];
    const float* pp2_g = (const float*)d_in[21];
    const float* pp2_be = (const float*)d_in[22];
    const float* m1_W = (const float*)d_in[23];
    const float* m1_b = (const float*)d_in[24];
    const float* m1_g = (const float*)d_in[25];
    const float* m1_be = (const float*)d_in[26];
    const float* m2_W = (const float*)d_in[27];
    const float* m2_b = (const float*)d_in[28];
    const float* m2_g = (const float*)d_in[29];
    const float* m2_be = (const float*)d_in[30];
    float* out = (float*)d_out;

    cudaFuncSetAttribute(wmma_gemm<0>, cudaFuncAttributeMaxDynamicSharedMemorySize, 92160);
    cudaFuncSetAttribute(wmma_gemm<1>, cudaFuncAttributeMaxDynamicSharedMemorySize, 46080);
    cudaFuncSetAttribute(wmma_gemm<2>, cudaFuncAttributeMaxDynamicSharedMemorySize, 69632);

    init_state<<<(NT * HD + 255) / 256, 256>>>(h0, c0, last_pos, last_pos_rel, emb_W, emb_b);
    fold_pp1<<<2, 256>>>(pp1_W, pp1_b, pp1_g, pp1_be, sp_W, sp_b);
    fold_LW<<<96, 256>>>(Wih, Whh, bih, bhh);
    prep_wB<0><<<512, 256>>>(pp2_W, pp2_b, pp2_g, pp2_be);
    prep_wB<1><<<512, 256>>>(m1_W, m1_b, m1_g, m1_be);
    prep_wB<2><<<128, 256>>>(m2_W, m2_b, m2_g, m2_be);

    for (int t = 0; t < TS; t++) {
        if (t == 0) tile_gemm<2, 1><<<dim3(4, NT / 32), 256>>>();  // gates (h from h0)
        else        tile_gemm<2, 0><<<dim3(4, NT / 32), 256>>>();  // gates (h = relu(sum hp + bm2))
        lstm_point<<<NT, 128>>>(pos_W, pos_b, emb_W, emb_b, out + (size_t)t * NT * 2);
        tile_gemm<0, 0><<<dim3(4, NT / 32), 256>>>();              // hpre
        build_x1<<<dim3(8, 8, SC), 256>>>();                       // x1 fp16 tiles
        wmma_gemm<0><<<dim3(8, 128), 256, 92160>>>();              // pool (3-stage pipe)
        wmma_gemm<1><<<dim3(8, 16), 256, 46080>>>();               // m1 (3-stage pipe)
        wmma_gemm<2><<<dim3(4, 8), 256, 69632>>>();                // m2 split-K partials
    }
    (void)in_sizes; (void)n_in; (void)out_size;
}

// round 13
// speedup vs baseline: 1.1462x; 1.1462x over previous
#include <cuda_runtime.h>
#include <cuda_fp16.h>
#include <mma.h>
#include <stdint.h>
#include <math.h>

using namespace nvcuda;

#define NT 1024
#define HD 128
#define ED 64
#define SC 32
#define PP 32
#define B1D 512
#define B2D 1024
#define M1D 1024
#define TS 12
#define KM1 (HD + B2D)   // 1152
#define BN_INV_F 0.9999950000374997f

// ---------------- device state / scratch ----------------
static __device__ float g_h[NT * HD];
static __device__ float g_c[NT * HD];
static __device__ float g_h2[NT * HD];
static __device__ float g_lp[NT * 2];
static __device__ float g_din[NT * ED];
static __device__ float g_hpre[NT * B1D];
static __device__ float g_gates[NT * 4 * HD];
static __device__ float g_hp[4 * NT * HD];     // m2 split-K partials
// folded scalar weights
static __device__ float g_A[B1D], g_B[B1D], g_bias1[B1D];
static __device__ float g_Wb[B1D * HD];
static __device__ float g_bias2[B2D], g_bm1[M1D], g_bm2[HD];
static __device__ float g_LW[4 * HD * 192], g_Lb[4 * HD];
// pre-tiled fp16 weights: [nb][chunk64][128r x 64k] tiles (8192 halfs)
static __device__ __half g_W2th[8 * 8 * 8192];
static __device__ __half g_M1th[8 * 18 * 8192];
static __device__ __half g_M2th[16 * 8192];
// activation tiles, fp16, [group][chunk64][128x64]
static __device__ __half g_x1h[256 * 8 * 8192];   // pool A
static __device__ __half g_mAh[8 * 18 * 8192];    // m1 A
static __device__ __half g_mBh[8 * 16 * 8192];    // m2 A

// ---------------- helpers ----------------
__device__ __forceinline__ uint32_t pack2hf(float v0, float v1) {
    __half2 h = __floats2half2_rn(v0, v1);
    return *(uint32_t*)&h;
}
__device__ __forceinline__ uint32_t smem_u32(const void* p) {
    uint32_t a;
    asm("{ .reg .u64 t; cvta.to.shared.u64 t, %1; cvt.u32.u64 %0, t; }" : "=r"(a) : "l"(p));
    return a;
}
__device__ __forceinline__ void cpa(uint32_t dsmem, const void* gsrc) {
    asm volatile("cp.async.cg.shared.global [%0], [%1], 16;" :: "r"(dsmem), "l"(gsrc) : "memory");
}
#define CPA_COMMIT() asm volatile("cp.async.commit_group;" ::: "memory")
#define CPA_WAIT1()  asm volatile("cp.async.wait_group 1;" ::: "memory")
#define CPA_WAIT0()  asm volatile("cp.async.wait_group 0;" ::: "memory")

// ---------------- prep kernels (once per launch) ----------------
__global__ void init_state(const float* __restrict__ h0, const float* __restrict__ c0,
                           const float* __restrict__ last_pos, const float* __restrict__ last_pos_rel,
                           const float* __restrict__ embW, const float* __restrict__ embb) {
    int idx = blockIdx.x * blockDim.x + threadIdx.x;
    if (idx < NT * HD) { g_h[idx] = h0[idx]; g_c[idx] = c0[idx]; }
    if (idx < NT * 2) g_lp[idx] = last_pos[idx];
    if (idx < NT * ED) {
        int n = idx / ED, e = idx % ED;
        g_din[idx] = last_pos_rel[n * 2] * embW[e * 2] +
                     last_pos_rel[n * 2 + 1] * embW[e * 2 + 1] + embb[e];
    }
}

__global__ void fold_pp1(const float* __restrict__ pp1_W, const float* __restrict__ pp1_b,
                         const float* __restrict__ pp1_g, const float* __restrict__ pp1_be,
                         const float* __restrict__ sp_W, const float* __restrict__ sp_b) {
    int k = blockIdx.x * blockDim.x + threadIdx.x;
    if (k >= B1D) return;
    float s1 = BN_INV_F * pp1_g[k];
    const float* row = pp1_W + (size_t)k * (ED + HD);
    float sa = 0.f, sb = 0.f, sc = 0.f;
    for (int e = 0; e < ED; e++) {
        float w = row[e];
        sa += w * sp_W[e * 2]; sb += w * sp_W[e * 2 + 1]; sc += w * sp_b[e];
    }
    g_A[k] = sa * s1; g_B[k] = sb * s1;
    g_bias1[k] = (pp1_b[k] + sc) * s1 + pp1_be[k];
    for (int h = 0; h < HD; h++) g_Wb[k * HD + h] = row[ED + h] * s1;
}

__global__ void fold_LW(const float* __restrict__ Wih, const float* __restrict__ Whh,
                        const float* __restrict__ bih, const float* __restrict__ bhh) {
    for (int idx = blockIdx.x * blockDim.x + threadIdx.x; idx < 512 * 192; idx += gridDim.x * blockDim.x) {
        int r = idx / 192, cc = idx % 192;
        g_LW[idx] = (cc < 64) ? Wih[r * 64 + cc] : Whh[r * 128 + cc - 64];
        if (cc == 0) g_Lb[r] = bih[r] + bhh[r];
    }
}

// fp16 pre-tiled weights. WM=0: W2(K=512), 1: m1(K=1152), 2: m2(K=1024,R=128)
template <int WM>
__global__ void prep_wB(const float* __restrict__ W, const float* __restrict__ b,
                        const float* __restrict__ g, const float* __restrict__ be) {
    constexpr int K = (WM == 0) ? B1D : (WM == 1) ? KM1 : M1D;
    constexpr int ROWS = (WM == 2) ? HD : 1024;
    constexpr int KC = K / 64;
    __half* oh = (WM == 0) ? g_W2th : (WM == 1) ? g_M1th : g_M2th;
    float* bo = (WM == 0) ? g_bias2 : (WM == 1) ? g_bm1 : g_bm2;
    int total = ROWS * (K / 2);
    for (int p = blockIdx.x * blockDim.x + threadIdx.x; p < total; p += gridDim.x * blockDim.x) {
        int co = p / (K / 2), kp = p % (K / 2), k = kp * 2;
        int nb = co >> 7, r = co & 127, c = k >> 6;
        float s = BN_INV_F * g[co];
        float v0 = W[(size_t)co * K + k] * s, v1 = W[(size_t)co * K + k + 1] * s;
        size_t woff = (size_t)(nb * KC + c) * 4096 + r * 32 + (kp & 31);
        ((uint32_t*)oh)[woff] = pack2hf(v0, v1);
        if (kp == 0) bo[co] = b[co] * s + be[co];
    }
}

// ---------------- SIMT GEMM: MODE 0 hpre(K=128), MODE 2 gates(K=192) ----------------
template <int MODE, int FIRST>
__global__ __launch_bounds__(256) void tile_gemm() {
    constexpr int K = (MODE == 0) ? HD : 192;
    constexpr int LDC = (MODE == 0) ? B1D : 512;
    const float* Wp = (MODE == 0) ? g_Wb : g_LW;
    const float* bp = (MODE == 0) ? g_bias1 : g_Lb;
    float* outp = (MODE == 0) ? g_hpre : g_gates;
    int c0 = blockIdx.x * 128, grp = blockIdx.y, tid = threadIdx.x;
    int tx = tid & 31, ty = tid >> 5;
    __shared__ float a_s[32][64];
    __shared__ float w_s[64][129];
    int nbase = grp * 32;
    float acc[4][4] = {};
    for (int k0 = 0; k0 < K; k0 += 64) {
        __syncthreads();
        for (int idx = tid; idx < 32 * 64; idx += 256) {
            int j = idx >> 6, k = idx & 63, kk = k0 + k;
            float v;
            if (MODE == 0) v = g_h2[(nbase + j) * HD + kk];
            else if (kk < 64) v = g_din[(nbase + j) * ED + kk];
            else {
                int ped = nbase + j, cc = kk - 64;
                if (FIRST) v = g_h[ped * HD + cc];
                else {
                    float sum = g_hp[(size_t)ped * HD + cc]
                              + g_hp[(size_t)(NT + ped) * HD + cc]
                              + g_hp[(size_t)(2 * NT + ped) * HD + cc]
                              + g_hp[(size_t)(3 * NT + ped) * HD + cc];
                    v = fmaxf(sum + g_bm2[cc], 0.f);
                }
            }
            a_s[j][k] = v;
        }
        for (int idx = tid; idx < 128 * 64; idx += 256) {
            int c = idx >> 6, k = idx & 63;
            w_s[k][c] = Wp[(size_t)(c0 + c) * K + k0 + k];
        }
        __syncthreads();
#pragma unroll 4
        for (int k = 0; k < 64; k++) {
            float xr[4], wr[4];
#pragma unroll
            for (int jj = 0; jj < 4; jj++) xr[jj] = a_s[ty + jj * 8][k];
#pragma unroll
            for (int cc = 0; cc < 4; cc++) wr[cc] = w_s[k][tx + cc * 32];
#pragma unroll
            for (int jj = 0; jj < 4; jj++)
#pragma unroll
                for (int cc = 0; cc < 4; cc++) acc[jj][cc] = fmaf(xr[jj], wr[cc], acc[jj][cc]);
        }
    }
#pragma unroll
    for (int jj = 0; jj < 4; jj++) {
        int n = nbase + ty + jj * 8;
#pragma unroll
        for (int cc = 0; cc < 4; cc++) {
            int c = c0 + tx + cc * 32;
            outp[(size_t)n * LDC + c] = acc[jj][cc] + bp[c];
        }
    }
}

// ---------------- LSTM pointwise + h2 pack into m1 A-tiles ----------------
__global__ __launch_bounds__(128) void lstm_point(
    const float* __restrict__ posW, const float* __restrict__ posb,
    const float* __restrict__ embW, const float* __restrict__ embb,
    float* __restrict__ out_t) {
    int n = blockIdx.x, t = threadIdx.x;
    __shared__ float red0[HD], red1[HD], hs2[HD], rp[2];
    float gi = g_gates[n * 512 + 0 * HD + t];
    float gf = g_gates[n * 512 + 1 * HD + t];
    float gg = g_gates[n * 512 + 2 * HD + t];
    float go = g_gates[n * 512 + 3 * HD + t];
    float ig = 1.f / (1.f + expf(-gi));
    float fg = 1.f / (1.f + expf(-gf));
    float gv = tanhf(gg);
    float og = 1.f / (1.f + expf(-go));
    float c2 = fg * g_c[n * HD + t] + ig * gv;
    float h2 = og * tanhf(c2);
    g_c[n * HD + t] = c2;
    g_h2[n * HD + t] = h2;
    hs2[t] = h2;
    red0[t] = h2 * posW[t]; red1[t] = h2 * posW[HD + t];
    __syncthreads();
    for (int s = 64; s > 0; s >>= 1) {
        if (t < s) { red0[t] += red0[t + s]; red1[t] += red1[t + s]; }
        __syncthreads();
    }
    if (t < 2) {
        float v = ((t == 0) ? red0[0] : red1[0]) + posb[t];
        rp[t] = v;
        out_t[n * 2 + t] = v;
        g_lp[n * 2 + t] += v;
    }
    __syncthreads();
    if (t < ED) g_din[n * ED + t] = fmaf(rp[0], embW[t * 2], fmaf(rp[1], embW[t * 2 + 1], embb[t]));
    if (t < 64) {
        int mb = n >> 7, m = n & 127;
        int c = t >> 5;
        ((uint32_t*)g_mAh)[(size_t)(mb * 18 + c) * 4096 + m * 32 + (t & 31)] =
            pack2hf(hs2[2 * t], hs2[2 * t + 1]);
    }
}

// ---------------- build x1 fp16 tiles (once per step) ----------------
__global__ __launch_bounds__(256) void build_x1() {
    int c = blockIdx.x, ib = blockIdx.y, s = blockIdx.z;
    int tid = threadIdx.x;
    __shared__ float rxs[128], rys[128];
    if (tid < 128) {
        int i = ib * 4 + (tid >> 5), j = tid & 31;
        float dx = g_lp[(s * 32 + j) * 2]     - g_lp[(s * 32 + i) * 2];
        float dy = g_lp[(s * 32 + j) * 2 + 1] - g_lp[(s * 32 + i) * 2 + 1];
        float nrm = fmaxf(sqrtf(dx * dx + dy * dy), 1e-12f);
        rxs[tid] = dx / nrm; rys[tid] = dy / nrm;
    }
    __syncthreads();
    int grp = s * 8 + ib;
    uint32_t* oh = (uint32_t*)g_x1h + (size_t)(grp * 8 + c) * 4096;
    int kp = tid & 31, k = c * 64 + kp * 2;
    float2 ab0 = *(const float2*)(g_A + k);
    float2 bb0 = *(const float2*)(g_B + k);
#pragma unroll
    for (int q = 0; q < 16; q++) {
        int m = (tid >> 5) + q * 8;
        int pj = s * 32 + (m & 31);
        float rx = rxs[m], ry = rys[m];
        float2 hp = *(const float2*)(g_hpre + (size_t)pj * B1D + k);
        float v0 = fmaxf(hp.x + rx * ab0.x + ry * bb0.x, 0.f);
        float v1 = fmaxf(hp.y + rx * ab0.y + ry * bb0.y, 0.f);
        oh[m * 32 + kp] = pack2hf(v0, v1);
    }
}

// ---------------- wmma fp16 single-pass GEMM, 2-stage pipe, 2 CTAs/SM ----------------
// GM=0: pool, grid(8 nb, 256 grp), ROWS=128, KC=16, warp tile 32x64, occ 2
// GM=1: m1,   grid(8 nb, 16),  ROWS=64, KC=36, warp tile 32x32
// GM=2: m2,   grid(4 ksl, 8),  ROWS=128, KC=8, warp tile 32x64
template <int GM>
__global__ __launch_bounds__(256, 2) void wmma_gemm() {
    constexpr int KC = (GM == 0) ? 16 : (GM == 1) ? 36 : 8;
    constexpr int ROWS = (GM == 1) ? 64 : 128;
    constexpr int NF = (GM == 1) ? 2 : 4;
    constexpr int WC = (GM == 1) ? 4 : 2;
    constexpr int SA = ROWS * 80;
    constexpr int SS = SA + 10240;
    extern __shared__ __align__(16) char smraw[];
    uint32_t base = smem_u32(smraw);
    float* c_s = (float*)smraw;

    int tid = threadIdx.x, w = tid >> 5;
    int wr = w / WC, wc = w % WC;
    int nbX = blockIdx.x, grpY = blockIdx.y;

    const __half* Ah_g = (GM == 0) ? g_x1h : (GM == 1) ? g_mAh : g_mBh;
    const __half* Wh_g = (GM == 0) ? g_W2th : (GM == 1) ? g_M1th : g_M2th;

    auto stage = [&](int buf, int c) {
        int tile0, sub, roff = 0, wtile;
        if (GM == 0) {
            int ch = c >> 1; sub = c & 1;
            tile0 = grpY * 8 + ch;
            wtile = nbX * 8 + ch;
        } else if (GM == 1) {
            int ch = c >> 1; sub = c & 1;
            tile0 = (grpY >> 1) * 18 + ch; roff = (grpY & 1) * 64;
            wtile = nbX * 18 + ch;
        } else {
            int gch = nbX * 8 + c; sub = gch & 1;
            tile0 = grpY * 16 + (gch >> 1);
            wtile = gch >> 1;
        }
        uint32_t sb = base + buf * SS;
        for (int i = tid; i < ROWS * 4; i += 256) {
            int r = i >> 2, seg = i & 3;
            size_t so = (size_t)tile0 * 8192 + (roff + r) * 64 + sub * 32 + seg * 8;
            cpa(sb + r * 80 + seg * 16, Ah_g + so);
        }
        for (int i = tid; i < 512; i += 256) {
            int r = i >> 2, seg = i & 3;
            size_t so = (size_t)wtile * 8192 + r * 64 + sub * 32 + seg * 8;
            cpa(sb + SA + r * 80 + seg * 16, Wh_g + so);
        }
        CPA_COMMIT();
    };

    wmma::fragment<wmma::accumulator, 16, 16, 16, float> acc[2][NF];
#pragma unroll
    for (int mf = 0; mf < 2; mf++)
#pragma unroll
        for (int nf = 0; nf < NF; nf++) wmma::fill_fragment(acc[mf][nf], 0.f);

    stage(0, 0);
    for (int c = 0; c < KC; c++) {
        if (c + 1 < KC) { stage((c + 1) & 1, c + 1); CPA_WAIT1(); } else { CPA_WAIT0(); }
        __syncthreads();
        const __half* sbuf = (const __half*)(smraw + (c & 1) * SS);
        const __half* whp = sbuf + SA / 2;
#pragma unroll
        for (int ks = 0; ks < 2; ks++) {
            wmma::fragment<wmma::matrix_a, 16, 16, 16, __half, wmma::row_major> af[2];
#pragma unroll
            for (int mf = 0; mf < 2; mf++)
                wmma::load_matrix_sync(af[mf], sbuf + (wr * 32 + mf * 16) * 40 + ks * 16, 40);
#pragma unroll
            for (int nf = 0; nf < NF; nf++) {
                wmma::fragment<wmma::matrix_b, 16, 16, 16, __half, wmma::col_major> bh;
                int coff = (wc * NF * 16 + nf * 16) * 40 + ks * 16;
                wmma::load_matrix_sync(bh, whp + coff, 40);
#pragma unroll
                for (int mf = 0; mf < 2; mf++)
                    wmma::mma_sync(acc[mf][nf], af[mf], bh, acc[mf][nf]);
            }
        }
        __syncthreads();
    }

    __syncthreads();
#pragma unroll
    for (int mf = 0; mf < 2; mf++)
#pragma unroll
        for (int nf = 0; nf < NF; nf++)
            wmma::store_matrix_sync(c_s + (wr * 32 + mf * 16) * 136 + wc * NF * 16 + nf * 16,
                                    acc[mf][nf], 136, wmma::mem_row_major);
    __syncthreads();

    if (GM == 0) {
        int s = grpY >> 3, ib = grpY & 7;
        {
            int il = tid >> 6, kp0 = tid & 63;
            int cc0 = kp0 * 2;
            float m0 = c_s[(il * 32) * 136 + cc0];
            float m1v = c_s[(il * 32) * 136 + cc0 + 1];
#pragma unroll 8
            for (int r = 1; r < 32; r++) {
                m0  = fmaxf(m0,  c_s[(il * 32 + r) * 136 + cc0]);
                m1v = fmaxf(m1v, c_s[(il * 32 + r) * 136 + cc0 + 1]);
            }
            int col = nbX * 128 + cc0;
            float v0 = fmaxf(m0 + g_bias2[col], 0.f);
            float v1 = fmaxf(m1v + g_bias2[col + 1], 0.f);
            int ped = s * 32 + ib * 4 + il;
            int mb = ped >> 7, m = ped & 127;
            int cch = 2 + nbX * 2 + (kp0 >> 5);
            ((uint32_t*)g_mAh)[(size_t)(mb * 18 + cch) * 4096 + m * 32 + (kp0 & 31)] =
                pack2hf(v0, v1);
        }
    } else if (GM == 1) {
        for (int p = tid; p < 4096; p += 256) {
            int r = p >> 6, kp = p & 63;
            int cc0 = kp * 2, col = nbX * 128 + cc0;
            float v0 = fmaxf(c_s[r * 136 + cc0]     + g_bm1[col], 0.f);
            float v1 = fmaxf(c_s[r * 136 + cc0 + 1] + g_bm1[col + 1], 0.f);
            int ped = grpY * 64 + r;
            int mb = ped >> 7, m = ped & 127;
            int cch = nbX * 2 + (kp >> 5);
            ((uint32_t*)g_mBh)[(size_t)(mb * 16 + cch) * 4096 + m * 32 + (kp & 31)] =
                pack2hf(v0, v1);
        }
    } else {
        float* dst = g_hp + (size_t)nbX * NT * HD + (size_t)grpY * 128 * HD;
        for (int p = tid; p < 16384; p += 256) {
            int r = p >> 7, cc = p & 127;
            dst[r * HD + cc] = c_s[r * 136 + cc];
        }
    }
}

// ---------------- host launch ----------------
extern "C" void kernel_launch(void* const* d_in, const int* in_sizes, int n_in,
                              void* d_out, int out_size) {
    const float* last_pos     = (const float*)d_in[0];
    const float* last_pos_rel = (const float*)d_in[1];
    const float* h0  = (const float*)d_in[2];
    const float* c0  = (const float*)d_in[3];
    const float* emb_W = (const float*)d_in[5];
    const float* emb_b = (const float*)d_in[6];
    const float* Wih = (const float*)d_in[7];
    const float* Whh = (const float*)d_in[8];
    const float* bih = (const float*)d_in[9];
    const float* bhh = (const float*)d_in[10];
    const float* pos_W = (const float*)d_in[11];
    const float* pos_b = (const float*)d_in[12];
    const float* sp_W = (const float*)d_in[13];
    const float* sp_b = (const float*)d_in[14];
    const float* pp1_W = (const float*)d_in[15];
    const float* pp1_b = (const float*)d_in[16];
    const float* pp1_g = (const float*)d_in[17];
    const float* pp1_be = (const float*)d_in[18];
    const float* pp2_W = (const float*)d_in[19];
    const float* pp2_b = (const float*)d_in[20];
    const float* pp2_g = (const float*)d_in[21];
    const float* pp2_be = (const float*)d_in[22];
    const float* m1_W = (const float*)d_in[23];
    const float* m1_b = (const float*)d_in[24];
    const float* m1_g = (const float*)d_in[25];
    const float* m1_be = (const float*)d_in[26];
    const float* m2_W = (const float*)d_in[27];
    const float* m2_b = (const float*)d_in[28];
    const float* m2_g = (const float*)d_in[29];
    const float* m2_be = (const float*)d_in[30];
    float* out = (float*)d_out;

    cudaFuncSetAttribute(wmma_gemm<0>, cudaFuncAttributeMaxDynamicSharedMemorySize, 69632);
    cudaFuncSetAttribute(wmma_gemm<1>, cudaFuncAttributeMaxDynamicSharedMemorySize, 36864);
    cudaFuncSetAttribute(wmma_gemm<2>, cudaFuncAttributeMaxDynamicSharedMemorySize, 69632);

    init_state<<<(NT * HD + 255) / 256, 256>>>(h0, c0, last_pos, last_pos_rel, emb_W, emb_b);
    fold_pp1<<<2, 256>>>(pp1_W, pp1_b, pp1_g, pp1_be, sp_W, sp_b);
    fold_LW<<<96, 256>>>(Wih, Whh, bih, bhh);
    prep_wB<0><<<512, 256>>>(pp2_W, pp2_b, pp2_g, pp2_be);
    prep_wB<1><<<512, 256>>>(m1_W, m1_b, m1_g, m1_be);
    prep_wB<2><<<128, 256>>>(m2_W, m2_b, m2_g, m2_be);

    for (int t = 0; t < TS; t++) {
        if (t == 0) tile_gemm<2, 1><<<dim3(4, NT / 32), 256>>>();  // gates (h from h0)
        else        tile_gemm<2, 0><<<dim3(4, NT / 32), 256>>>();  // gates (h = relu(sum hp + bm2))
        lstm_point<<<NT, 128>>>(pos_W, pos_b, emb_W, emb_b, out + (size_t)t * NT * 2);
        tile_gemm<0, 0><<<dim3(4, NT / 32), 256>>>();              // hpre
        build_x1<<<dim3(8, 8, SC), 256>>>();                       // x1 fp16 tiles
        wmma_gemm<0><<<dim3(8, 256), 256, 69632>>>();              // pool (2 CTAs/SM)
        wmma_gemm<1><<<dim3(8, 16), 256, 36864>>>();               // m1
        wmma_gemm<2><<<dim3(4, 8), 256, 69632>>>();                // m2 split-K partials
    }
    (void)in_sizes; (void)n_in; (void)out_size;
}

// round 14
// speedup vs baseline: 1.1854x; 1.0343x over previous
#include <cuda_runtime.h>
#include <cuda_fp16.h>
#include <mma.h>
#include <stdint.h>
#include <math.h>

using namespace nvcuda;

#define NT 1024
#define HD 128
#define ED 64
#define SC 32
#define PP 32
#define B1D 512
#define B2D 1024
#define M1D 1024
#define TS 12
#define KM1 (HD + B2D)   // 1152
#define BN_INV_F 0.9999950000374997f

// ---------------- device state / scratch ----------------
static __device__ float g_h[NT * HD];
static __device__ float g_c[NT * HD];
static __device__ float g_h2[NT * HD];
static __device__ float g_lp[NT * 2];
static __device__ float g_din[NT * ED];
static __device__ float g_hpre[NT * B1D];
static __device__ float g_gates[NT * 4 * HD];
static __device__ float g_hp[4 * NT * HD];     // m2 split-K partials
// folded scalar weights
static __device__ float g_A[B1D], g_B[B1D], g_bias1[B1D];
static __device__ float g_Wb[B1D * HD];
static __device__ float g_bias2[B2D], g_bm1[M1D], g_bm2[HD];
static __device__ float g_LW[4 * HD * 192], g_Lb[4 * HD];
// pre-tiled fp16 weights: [nb][chunk64][128r x 64k] tiles (8192 halfs)
static __device__ __half g_W2th[8 * 8 * 8192];
static __device__ __half g_M1th[8 * 18 * 8192];
static __device__ __half g_M2th[16 * 8192];
// activation tiles, fp16, [group][chunk64][128x64]
static __device__ __half g_x1h[256 * 8 * 8192];   // pool A
static __device__ __half g_mAh[8 * 18 * 8192];    // m1 A
static __device__ __half g_mBh[8 * 16 * 8192];    // m2 A

// ---------------- helpers ----------------
__device__ __forceinline__ uint32_t pack2hf(float v0, float v1) {
    __half2 h = __floats2half2_rn(v0, v1);
    return *(uint32_t*)&h;
}
__device__ __forceinline__ uint32_t smem_u32(const void* p) {
    uint32_t a;
    asm("{ .reg .u64 t; cvta.to.shared.u64 t, %1; cvt.u32.u64 %0, t; }" : "=r"(a) : "l"(p));
    return a;
}
__device__ __forceinline__ void cpa(uint32_t dsmem, const void* gsrc) {
    asm volatile("cp.async.cg.shared.global [%0], [%1], 16;" :: "r"(dsmem), "l"(gsrc) : "memory");
}
#define CPA_COMMIT() asm volatile("cp.async.commit_group;" ::: "memory")
#define CPA_WAIT1()  asm volatile("cp.async.wait_group 1;" ::: "memory")
#define CPA_WAIT0()  asm volatile("cp.async.wait_group 0;" ::: "memory")

// ---------------- consolidated prep (single launch) ----------------
// blocks 0..255:   W2 split (262144 pairs)
// blocks 256..767: m1 split (589824 pairs)
// blocks 768..831: m2 split (65536 pairs)
// blocks 832..895: LW fold (98304 elems)
// blocks 896..897: pp1 fold (512 rows)
// blocks 898..1023: init_state (131072 elems)
__global__ __launch_bounds__(256) void prep_all(
    const float* __restrict__ h0, const float* __restrict__ c0,
    const float* __restrict__ last_pos, const float* __restrict__ last_pos_rel,
    const float* __restrict__ embW, const float* __restrict__ embb,
    const float* __restrict__ Wih, const float* __restrict__ Whh,
    const float* __restrict__ bih, const float* __restrict__ bhh,
    const float* __restrict__ sp_W, const float* __restrict__ sp_b,
    const float* __restrict__ pp1_W, const float* __restrict__ pp1_b,
    const float* __restrict__ pp1_g, const float* __restrict__ pp1_be,
    const float* __restrict__ pp2_W, const float* __restrict__ pp2_b,
    const float* __restrict__ pp2_g, const float* __restrict__ pp2_be,
    const float* __restrict__ m1_W, const float* __restrict__ m1_b,
    const float* __restrict__ m1_g, const float* __restrict__ m1_be,
    const float* __restrict__ m2_W, const float* __restrict__ m2_b,
    const float* __restrict__ m2_g, const float* __restrict__ m2_be) {
    int bid = blockIdx.x, tid = threadIdx.x;
    if (bid < 256) {
        // W2: K=512, ROWS=1024, KC=8
        for (int p = bid * 256 + tid; p < 1024 * 256; p += 256 * 256) {
            int co = p >> 8, kp = p & 255, k = kp * 2;
            int nb = co >> 7, r = co & 127, c = k >> 6;
            float s = BN_INV_F * pp2_g[co];
            float v0 = pp2_W[(size_t)co * B1D + k] * s, v1 = pp2_W[(size_t)co * B1D + k + 1] * s;
            ((uint32_t*)g_W2th)[(size_t)(nb * 8 + c) * 4096 + r * 32 + (kp & 31)] = pack2hf(v0, v1);
            if (kp == 0) g_bias2[co] = pp2_b[co] * s + pp2_be[co];
        }
    } else if (bid < 768) {
        // m1: K=1152, ROWS=1024, KC=18
        for (int p = (bid - 256) * 256 + tid; p < 1024 * 576; p += 512 * 256) {
            int co = p / 576, kp = p % 576, k = kp * 2;
            int nb = co >> 7, r = co & 127, c = k >> 6;
            float s = BN_INV_F * m1_g[co];
            float v0 = m1_W[(size_t)co * KM1 + k] * s, v1 = m1_W[(size_t)co * KM1 + k + 1] * s;
            ((uint32_t*)g_M1th)[(size_t)(nb * 18 + c) * 4096 + r * 32 + (kp & 31)] = pack2hf(v0, v1);
            if (kp == 0) g_bm1[co] = m1_b[co] * s + m1_be[co];
        }
    } else if (bid < 832) {
        // m2: K=1024, ROWS=128, KC=16
        for (int p = (bid - 768) * 256 + tid; p < 128 * 512; p += 64 * 256) {
            int co = p >> 9, kp = p & 511, k = kp * 2;
            int r = co & 127, c = k >> 6;
            float s = BN_INV_F * m2_g[co];
            float v0 = m2_W[(size_t)co * M1D + k] * s, v1 = m2_W[(size_t)co * M1D + k + 1] * s;
            ((uint32_t*)g_M2th)[(size_t)c * 4096 + r * 32 + (kp & 31)] = pack2hf(v0, v1);
            if (kp == 0) g_bm2[co] = m2_b[co] * s + m2_be[co];
        }
    } else if (bid < 896) {
        for (int idx = (bid - 832) * 256 + tid; idx < 512 * 192; idx += 64 * 256) {
            int r = idx / 192, cc = idx % 192;
            g_LW[idx] = (cc < 64) ? Wih[r * 64 + cc] : Whh[r * 128 + cc - 64];
            if (cc == 0) g_Lb[r] = bih[r] + bhh[r];
        }
    } else if (bid < 898) {
        int k = (bid - 896) * 256 + tid;
        if (k < B1D) {
            float s1 = BN_INV_F * pp1_g[k];
            const float* row = pp1_W + (size_t)k * (ED + HD);
            float sa = 0.f, sb = 0.f, sc = 0.f;
            for (int e = 0; e < ED; e++) {
                float w = row[e];
                sa += w * sp_W[e * 2]; sb += w * sp_W[e * 2 + 1]; sc += w * sp_b[e];
            }
            g_A[k] = sa * s1; g_B[k] = sb * s1;
            g_bias1[k] = (pp1_b[k] + sc) * s1 + pp1_be[k];
            for (int h = 0; h < HD; h++) g_Wb[k * HD + h] = row[ED + h] * s1;
        }
    } else {
        for (int idx = (bid - 898) * 256 + tid; idx < NT * HD; idx += 126 * 256) {
            g_h[idx] = h0[idx]; g_c[idx] = c0[idx];
            if (idx < NT * 2) g_lp[idx] = last_pos[idx];
            if (idx < NT * ED) {
                int n = idx / ED, e = idx % ED;
                g_din[idx] = last_pos_rel[n * 2] * embW[e * 2] +
                             last_pos_rel[n * 2 + 1] * embW[e * 2 + 1] + embb[e];
            }
        }
    }
}

// ---------------- SIMT GEMM: MODE 0 hpre(K=128), MODE 2 gates(K=192) ----------------
template <int MODE, int FIRST>
__global__ __launch_bounds__(256) void tile_gemm() {
    constexpr int K = (MODE == 0) ? HD : 192;
    constexpr int LDC = (MODE == 0) ? B1D : 512;
    const float* Wp = (MODE == 0) ? g_Wb : g_LW;
    const float* bp = (MODE == 0) ? g_bias1 : g_Lb;
    float* outp = (MODE == 0) ? g_hpre : g_gates;
    int c0 = blockIdx.x * 128, grp = blockIdx.y, tid = threadIdx.x;
    int tx = tid & 31, ty = tid >> 5;
    __shared__ float a_s[32][64];
    __shared__ float w_s[64][129];
    int nbase = grp * 32;
    float acc[4][4] = {};
    for (int k0 = 0; k0 < K; k0 += 64) {
        __syncthreads();
        for (int idx = tid; idx < 32 * 64; idx += 256) {
            int j = idx >> 6, k = idx & 63, kk = k0 + k;
            float v;
            if (MODE == 0) v = g_h2[(nbase + j) * HD + kk];
            else if (kk < 64) v = g_din[(nbase + j) * ED + kk];
            else {
                int ped = nbase + j, cc = kk - 64;
                if (FIRST) v = g_h[ped * HD + cc];
                else {
                    float sum = g_hp[(size_t)ped * HD + cc]
                              + g_hp[(size_t)(NT + ped) * HD + cc]
                              + g_hp[(size_t)(2 * NT + ped) * HD + cc]
                              + g_hp[(size_t)(3 * NT + ped) * HD + cc];
                    v = fmaxf(sum + g_bm2[cc], 0.f);
                }
            }
            a_s[j][k] = v;
        }
        for (int idx = tid; idx < 128 * 64; idx += 256) {
            int c = idx >> 6, k = idx & 63;
            w_s[k][c] = Wp[(size_t)(c0 + c) * K + k0 + k];
        }
        __syncthreads();
#pragma unroll 4
        for (int k = 0; k < 64; k++) {
            float xr[4], wr[4];
#pragma unroll
            for (int jj = 0; jj < 4; jj++) xr[jj] = a_s[ty + jj * 8][k];
#pragma unroll
            for (int cc = 0; cc < 4; cc++) wr[cc] = w_s[k][tx + cc * 32];
#pragma unroll
            for (int jj = 0; jj < 4; jj++)
#pragma unroll
                for (int cc = 0; cc < 4; cc++) acc[jj][cc] = fmaf(xr[jj], wr[cc], acc[jj][cc]);
        }
    }
#pragma unroll
    for (int jj = 0; jj < 4; jj++) {
        int n = nbase + ty + jj * 8;
#pragma unroll
        for (int cc = 0; cc < 4; cc++) {
            int c = c0 + tx + cc * 32;
            outp[(size_t)n * LDC + c] = acc[jj][cc] + bp[c];
        }
    }
}

// ---------------- LSTM pointwise + h2 pack into m1 A-tiles ----------------
__global__ __launch_bounds__(128) void lstm_point(
    const float* __restrict__ posW, const float* __restrict__ posb,
    const float* __restrict__ embW, const float* __restrict__ embb,
    float* __restrict__ out_t) {
    int n = blockIdx.x, t = threadIdx.x;
    __shared__ float red0[HD], red1[HD], hs2[HD], rp[2];
    float gi = g_gates[n * 512 + 0 * HD + t];
    float gf = g_gates[n * 512 + 1 * HD + t];
    float gg = g_gates[n * 512 + 2 * HD + t];
    float go = g_gates[n * 512 + 3 * HD + t];
    float ig = 1.f / (1.f + expf(-gi));
    float fg = 1.f / (1.f + expf(-gf));
    float gv = tanhf(gg);
    float og = 1.f / (1.f + expf(-go));
    float c2 = fg * g_c[n * HD + t] + ig * gv;
    float h2 = og * tanhf(c2);
    g_c[n * HD + t] = c2;
    g_h2[n * HD + t] = h2;
    hs2[t] = h2;
    red0[t] = h2 * posW[t]; red1[t] = h2 * posW[HD + t];
    __syncthreads();
    for (int s = 64; s > 0; s >>= 1) {
        if (t < s) { red0[t] += red0[t + s]; red1[t] += red1[t + s]; }
        __syncthreads();
    }
    if (t < 2) {
        float v = ((t == 0) ? red0[0] : red1[0]) + posb[t];
        rp[t] = v;
        out_t[n * 2 + t] = v;
        g_lp[n * 2 + t] += v;
    }
    __syncthreads();
    if (t < ED) g_din[n * ED + t] = fmaf(rp[0], embW[t * 2], fmaf(rp[1], embW[t * 2 + 1], embb[t]));
    if (t < 64) {
        int mb = n >> 7, m = n & 127;
        int c = t >> 5;
        ((uint32_t*)g_mAh)[(size_t)(mb * 18 + c) * 4096 + m * 32 + (t & 31)] =
            pack2hf(hs2[2 * t], hs2[2 * t + 1]);
    }
}

// ---------------- build x1 fp16 tiles (once per step) ----------------
__global__ __launch_bounds__(256) void build_x1() {
    int c = blockIdx.x, ib = blockIdx.y, s = blockIdx.z;
    int tid = threadIdx.x;
    __shared__ float rxs[128], rys[128];
    if (tid < 128) {
        int i = ib * 4 + (tid >> 5), j = tid & 31;
        float dx = g_lp[(s * 32 + j) * 2]     - g_lp[(s * 32 + i) * 2];
        float dy = g_lp[(s * 32 + j) * 2 + 1] - g_lp[(s * 32 + i) * 2 + 1];
        float nrm = fmaxf(sqrtf(dx * dx + dy * dy), 1e-12f);
        rxs[tid] = dx / nrm; rys[tid] = dy / nrm;
    }
    __syncthreads();
    int grp = s * 8 + ib;
    uint32_t* oh = (uint32_t*)g_x1h + (size_t)(grp * 8 + c) * 4096;
    int kp = tid & 31, k = c * 64 + kp * 2;
    float2 ab0 = *(const float2*)(g_A + k);
    float2 bb0 = *(const float2*)(g_B + k);
#pragma unroll
    for (int q = 0; q < 16; q++) {
        int m = (tid >> 5) + q * 8;
        int pj = s * 32 + (m & 31);
        float rx = rxs[m], ry = rys[m];
        float2 hp = *(const float2*)(g_hpre + (size_t)pj * B1D + k);
        float v0 = fmaxf(hp.x + rx * ab0.x + ry * bb0.x, 0.f);
        float v1 = fmaxf(hp.y + rx * ab0.y + ry * bb0.y, 0.f);
        oh[m * 32 + kp] = pack2hf(v0, v1);
    }
}

// ---------------- pool wmma: k=64 chunks (KC=8), 2-stage, 2 CTAs/SM ----------------
// grid(8 nb, 256 grp); warp tile 32x64 (4 wr x 2 wc); smem stage 36864 x2 = 73728.
#define POOL_SS 36864
#define POOL_SMEM 73728

__global__ __launch_bounds__(256, 2) void pool_gemm() {
    extern __shared__ __align__(16) char smraw[];
    uint32_t base = smem_u32(smraw);
    float* c_s = (float*)smraw;
    int tid = threadIdx.x, w = tid >> 5;
    int wr = w >> 1, wc = w & 1;
    int nbX = blockIdx.x, grpY = blockIdx.y;

    auto stage = [&](int buf, int c) {
        uint32_t sb = base + buf * POOL_SS;
        const __half* At = g_x1h + (size_t)(grpY * 8 + c) * 8192;
        const __half* Wt = g_W2th + (size_t)(nbX * 8 + c) * 8192;
#pragma unroll
        for (int q = 0; q < 4; q++) {
            int i = tid + q * 256;                 // 0..1023
            int r = i >> 3, seg = i & 7;
            cpa(sb + r * 144 + seg * 16, At + r * 64 + seg * 8);
            cpa(sb + 18432 + r * 144 + seg * 16, Wt + r * 64 + seg * 8);
        }
        CPA_COMMIT();
    };

    wmma::fragment<wmma::accumulator, 16, 16, 16, float> acc[2][4];
#pragma unroll
    for (int mf = 0; mf < 2; mf++)
#pragma unroll
        for (int nf = 0; nf < 4; nf++) wmma::fill_fragment(acc[mf][nf], 0.f);

    stage(0, 0);
    for (int c = 0; c < 8; c++) {
        if (c + 1 < 8) { stage((c + 1) & 1, c + 1); CPA_WAIT1(); } else { CPA_WAIT0(); }
        __syncthreads();
        const __half* sbuf = (const __half*)(smraw + (c & 1) * POOL_SS);
        const __half* whp = sbuf + 9216;
#pragma unroll
        for (int ks = 0; ks < 4; ks++) {
            wmma::fragment<wmma::matrix_a, 16, 16, 16, __half, wmma::row_major> af[2];
#pragma unroll
            for (int mf = 0; mf < 2; mf++)
                wmma::load_matrix_sync(af[mf], sbuf + (wr * 32 + mf * 16) * 72 + ks * 16, 72);
#pragma unroll
            for (int nf = 0; nf < 4; nf++) {
                wmma::fragment<wmma::matrix_b, 16, 16, 16, __half, wmma::col_major> bh;
                wmma::load_matrix_sync(bh, whp + (wc * 64 + nf * 16) * 72 + ks * 16, 72);
#pragma unroll
                for (int mf = 0; mf < 2; mf++)
                    wmma::mma_sync(acc[mf][nf], af[mf], bh, acc[mf][nf]);
            }
        }
        __syncthreads();
    }

    __syncthreads();
#pragma unroll
    for (int mf = 0; mf < 2; mf++)
#pragma unroll
        for (int nf = 0; nf < 4; nf++)
            wmma::store_matrix_sync(c_s + (wr * 32 + mf * 16) * 136 + wc * 64 + nf * 16,
                                    acc[mf][nf], 136, wmma::mem_row_major);
    __syncthreads();

    int s = grpY >> 3, ib = grpY & 7;
    {
        int il = tid >> 6, kp0 = tid & 63;
        int cc0 = kp0 * 2;
        float m0 = c_s[(il * 32) * 136 + cc0];
        float m1v = c_s[(il * 32) * 136 + cc0 + 1];
#pragma unroll 8
        for (int r = 1; r < 32; r++) {
            m0  = fmaxf(m0,  c_s[(il * 32 + r) * 136 + cc0]);
            m1v = fmaxf(m1v, c_s[(il * 32 + r) * 136 + cc0 + 1]);
        }
        int col = nbX * 128 + cc0;
        float v0 = fmaxf(m0 + g_bias2[col], 0.f);
        float v1 = fmaxf(m1v + g_bias2[col + 1], 0.f);
        int ped = s * 32 + ib * 4 + il;
        int mb = ped >> 7, m = ped & 127;
        int cch = 2 + nbX * 2 + (kp0 >> 5);
        ((uint32_t*)g_mAh)[(size_t)(mb * 18 + cch) * 4096 + m * 32 + (kp0 & 31)] =
            pack2hf(v0, v1);
    }
}

// ---------------- m1 / m2 wmma (R13 structure) ----------------
// GM=1: m1, grid(8 nb, 16), ROWS=64, KC=36, warp tile 32x32
// GM=2: m2, grid(4 ksl, 8), ROWS=128, KC=8, warp tile 32x64
template <int GM>
__global__ __launch_bounds__(256, 2) void wmma_gemm() {
    constexpr int KC = (GM == 1) ? 36 : 8;
    constexpr int ROWS = (GM == 1) ? 64 : 128;
    constexpr int NF = (GM == 1) ? 2 : 4;
    constexpr int WC = (GM == 1) ? 4 : 2;
    constexpr int SA = ROWS * 80;
    constexpr int SS = SA + 10240;
    extern __shared__ __align__(16) char smraw[];
    uint32_t base = smem_u32(smraw);
    float* c_s = (float*)smraw;

    int tid = threadIdx.x, w = tid >> 5;
    int wr = w / WC, wc = w % WC;
    int nbX = blockIdx.x, grpY = blockIdx.y;

    const __half* Ah_g = (GM == 1) ? g_mAh : g_mBh;
    const __half* Wh_g = (GM == 1) ? g_M1th : g_M2th;

    auto stage = [&](int buf, int c) {
        int tile0, sub, roff = 0, wtile;
        if (GM == 1) {
            int ch = c >> 1; sub = c & 1;
            tile0 = (grpY >> 1) * 18 + ch; roff = (grpY & 1) * 64;
            wtile = nbX * 18 + ch;
        } else {
            int gch = nbX * 8 + c; sub = gch & 1;
            tile0 = grpY * 16 + (gch >> 1);
            wtile = gch >> 1;
        }
        uint32_t sb = base + buf * SS;
        for (int i = tid; i < ROWS * 4; i += 256) {
            int r = i >> 2, seg = i & 3;
            size_t so = (size_t)tile0 * 8192 + (roff + r) * 64 + sub * 32 + seg * 8;
            cpa(sb + r * 80 + seg * 16, Ah_g + so);
        }
        for (int i = tid; i < 512; i += 256) {
            int r = i >> 2, seg = i & 3;
            size_t so = (size_t)wtile * 8192 + r * 64 + sub * 32 + seg * 8;
            cpa(sb + SA + r * 80 + seg * 16, Wh_g + so);
        }
        CPA_COMMIT();
    };

    wmma::fragment<wmma::accumulator, 16, 16, 16, float> acc[2][NF];
#pragma unroll
    for (int mf = 0; mf < 2; mf++)
#pragma unroll
        for (int nf = 0; nf < NF; nf++) wmma::fill_fragment(acc[mf][nf], 0.f);

    stage(0, 0);
    for (int c = 0; c < KC; c++) {
        if (c + 1 < KC) { stage((c + 1) & 1, c + 1); CPA_WAIT1(); } else { CPA_WAIT0(); }
        __syncthreads();
        const __half* sbuf = (const __half*)(smraw + (c & 1) * SS);
        const __half* whp = sbuf + SA / 2;
#pragma unroll
        for (int ks = 0; ks < 2; ks++) {
            wmma::fragment<wmma::matrix_a, 16, 16, 16, __half, wmma::row_major> af[2];
#pragma unroll
            for (int mf = 0; mf < 2; mf++)
                wmma::load_matrix_sync(af[mf], sbuf + (wr * 32 + mf * 16) * 40 + ks * 16, 40);
#pragma unroll
            for (int nf = 0; nf < NF; nf++) {
                wmma::fragment<wmma::matrix_b, 16, 16, 16, __half, wmma::col_major> bh;
                int coff = (wc * NF * 16 + nf * 16) * 40 + ks * 16;
                wmma::load_matrix_sync(bh, whp + coff, 40);
#pragma unroll
                for (int mf = 0; mf < 2; mf++)
                    wmma::mma_sync(acc[mf][nf], af[mf], bh, acc[mf][nf]);
            }
        }
        __syncthreads();
    }

    __syncthreads();
#pragma unroll
    for (int mf = 0; mf < 2; mf++)
#pragma unroll
        for (int nf = 0; nf < NF; nf++)
            wmma::store_matrix_sync(c_s + (wr * 32 + mf * 16) * 136 + wc * NF * 16 + nf * 16,
                                    acc[mf][nf], 136, wmma::mem_row_major);
    __syncthreads();

    if (GM == 1) {
        for (int p = tid; p < 4096; p += 256) {
            int r = p >> 6, kp = p & 63;
            int cc0 = kp * 2, col = nbX * 128 + cc0;
            float v0 = fmaxf(c_s[r * 136 + cc0]     + g_bm1[col], 0.f);
            float v1 = fmaxf(c_s[r * 136 + cc0 + 1] + g_bm1[col + 1], 0.f);
            int ped = grpY * 64 + r;
            int mb = ped >> 7, m = ped & 127;
            int cch = nbX * 2 + (kp >> 5);
            ((uint32_t*)g_mBh)[(size_t)(mb * 16 + cch) * 4096 + m * 32 + (kp & 31)] =
                pack2hf(v0, v1);
        }
    } else {
        float* dst = g_hp + (size_t)nbX * NT * HD + (size_t)grpY * 128 * HD;
        for (int p = tid; p < 16384; p += 256) {
            int r = p >> 7, cc = p & 127;
            dst[r * HD + cc] = c_s[r * 136 + cc];
        }
    }
}

// ---------------- host launch ----------------
extern "C" void kernel_launch(void* const* d_in, const int* in_sizes, int n_in,
                              void* d_out, int out_size) {
    const float* last_pos     = (const float*)d_in[0];
    const float* last_pos_rel = (const float*)d_in[1];
    const float* h0  = (const float*)d_in[2];
    const float* c0  = (const float*)d_in[3];
    const float* emb_W = (const float*)d_in[5];
    const float* emb_b = (const float*)d_in[6];
    const float* Wih = (const float*)d_in[7];
    const float* Whh = (const float*)d_in[8];
    const float* bih = (const float*)d_in[9];
    const float* bhh = (const float*)d_in[10];
    const float* pos_W = (const float*)d_in[11];
    const float* pos_b = (const float*)d_in[12];
    const float* sp_W = (const float*)d_in[13];
    const float* sp_b = (const float*)d_in[14];
    const float* pp1_W = (const float*)d_in[15];
    const float* pp1_b = (const float*)d_in[16];
    const float* pp1_g = (const float*)d_in[17];
    const float* pp1_be = (const float*)d_in[18];
    const float* pp2_W = (const float*)d_in[19];
    const float* pp2_b = (const float*)d_in[20];
    const float* pp2_g = (const float*)d_in[21];
    const float* pp2_be = (const float*)d_in[22];
    const float* m1_W = (const float*)d_in[23];
    const float* m1_b = (const float*)d_in[24];
    const float* m1_g = (const float*)d_in[25];
    const float* m1_be = (const float*)d_in[26];
    const float* m2_W = (const float*)d_in[27];
    const float* m2_b = (const float*)d_in[28];
    const float* m2_g = (const float*)d_in[29];
    const float* m2_be = (const float*)d_in[30];
    float* out = (float*)d_out;

    cudaFuncSetAttribute(pool_gemm, cudaFuncAttributeMaxDynamicSharedMemorySize, POOL_SMEM);
    cudaFuncSetAttribute(wmma_gemm<1>, cudaFuncAttributeMaxDynamicSharedMemorySize, 36864);
    cudaFuncSetAttribute(wmma_gemm<2>, cudaFuncAttributeMaxDynamicSharedMemorySize, 69632);

    prep_all<<<1024, 256>>>(h0, c0, last_pos, last_pos_rel, emb_W, emb_b,
                            Wih, Whh, bih, bhh, sp_W, sp_b,
                            pp1_W, pp1_b, pp1_g, pp1_be,
                            pp2_W, pp2_b, pp2_g, pp2_be,
                            m1_W, m1_b, m1_g, m1_be,
                            m2_W, m2_b, m2_g, m2_be);

    for (int t = 0; t < TS; t++) {
        if (t == 0) tile_gemm<2, 1><<<dim3(4, NT / 32), 256>>>();  // gates (h from h0)
        else        tile_gemm<2, 0><<<dim3(4, NT / 32), 256>>>();  // gates
        lstm_point<<<NT, 128>>>(pos_W, pos_b, emb_W, emb_b, out + (size_t)t * NT * 2);
        tile_gemm<0, 0><<<dim3(4, NT / 32), 256>>>();              // hpre
        build_x1<<<dim3(8, 8, SC), 256>>>();                       // x1 fp16 tiles
        pool_gemm<<<dim3(8, 256), 256, POOL_SMEM>>>();             // pool (k=64 chunks)
        wmma_gemm<1><<<dim3(8, 16), 256, 36864>>>();               // m1
        wmma_gemm<2><<<dim3(4, 8), 256, 69632>>>();                // m2 split-K partials
    }
    (void)in_sizes; (void)n_in; (void)out_size;
}

// round 15
// speedup vs baseline: 1.2368x; 1.0433x over previous
#include <cuda_runtime.h>
#include <cuda_fp16.h>
#include <mma.h>
#include <stdint.h>
#include <math.h>

using namespace nvcuda;

#define NT 1024
#define HD 128
#define ED 64
#define SC 32
#define PP 32
#define B1D 512
#define B2D 1024
#define M1D 1024
#define TS 12
#define KM1 (HD + B2D)   // 1152
#define BN_INV_F 0.9999950000374997f

// ---------------- device state / scratch ----------------
static __device__ float g_h[NT * HD];
static __device__ float g_c[NT * HD];
static __device__ float g_lp[NT * 2];
static __device__ float g_din[NT * ED];
static __device__ float g_hpre[NT * B1D];
static __device__ float g_gates[NT * 4 * HD];
static __device__ float g_hp[4 * NT * HD];     // m2 split-K partials
// folded scalar weights
static __device__ float g_A[B1D], g_B[B1D], g_bias1[B1D];
static __device__ float g_bias2[B2D], g_bm1[M1D], g_bm2[HD];
static __device__ float g_LW[4 * HD * 192], g_Lb[4 * HD];
// pre-tiled fp16 weights: [nb][chunk64][128r x 64k] tiles (8192 halfs)
static __device__ __half g_W2th[8 * 8 * 8192];
static __device__ __half g_M1th[8 * 18 * 8192];
static __device__ __half g_M2th[16 * 8192];
static __device__ __half g_Wbth[4 * 2 * 8192];    // hpre weights (pp1 h-part, folded)
// activation tiles, fp16, [group][chunk64][128x64]
static __device__ __half g_x1h[256 * 8 * 8192];   // pool A
static __device__ __half g_mAh[8 * 18 * 8192];    // m1 A (chunks 0..1 = h2 -> also hpre A)
static __device__ __half g_mBh[8 * 16 * 8192];    // m2 A

// ---------------- helpers ----------------
__device__ __forceinline__ uint32_t pack2hf(float v0, float v1) {
    __half2 h = __floats2half2_rn(v0, v1);
    return *(uint32_t*)&h;
}
__device__ __forceinline__ uint32_t smem_u32(const void* p) {
    uint32_t a;
    asm("{ .reg .u64 t; cvta.to.shared.u64 t, %1; cvt.u32.u64 %0, t; }" : "=r"(a) : "l"(p));
    return a;
}
__device__ __forceinline__ void cpa(uint32_t dsmem, const void* gsrc) {
    asm volatile("cp.async.cg.shared.global [%0], [%1], 16;" :: "r"(dsmem), "l"(gsrc) : "memory");
}
#define CPA_COMMIT() asm volatile("cp.async.commit_group;" ::: "memory")
#define CPA_WAIT1()  asm volatile("cp.async.wait_group 1;" ::: "memory")
#define CPA_WAIT0()  asm volatile("cp.async.wait_group 0;" ::: "memory")

// ---------------- consolidated prep (single launch) ----------------
__global__ __launch_bounds__(256) void prep_all(
    const float* __restrict__ h0, const float* __restrict__ c0,
    const float* __restrict__ last_pos, const float* __restrict__ last_pos_rel,
    const float* __restrict__ embW, const float* __restrict__ embb,
    const float* __restrict__ Wih, const float* __restrict__ Whh,
    const float* __restrict__ bih, const float* __restrict__ bhh,
    const float* __restrict__ sp_W, const float* __restrict__ sp_b,
    const float* __restrict__ pp1_W, const float* __restrict__ pp1_b,
    const float* __restrict__ pp1_g, const float* __restrict__ pp1_be,
    const float* __restrict__ pp2_W, const float* __restrict__ pp2_b,
    const float* __restrict__ pp2_g, const float* __restrict__ pp2_be,
    const float* __restrict__ m1_W, const float* __restrict__ m1_b,
    const float* __restrict__ m1_g, const float* __restrict__ m1_be,
    const float* __restrict__ m2_W, const float* __restrict__ m2_b,
    const float* __restrict__ m2_g, const float* __restrict__ m2_be) {
    int bid = blockIdx.x, tid = threadIdx.x;
    if (bid < 256) {
        // W2: K=512, ROWS=1024, KC=8
        for (int p = bid * 256 + tid; p < 1024 * 256; p += 256 * 256) {
            int co = p >> 8, kp = p & 255, k = kp * 2;
            int nb = co >> 7, r = co & 127, c = k >> 6;
            float s = BN_INV_F * pp2_g[co];
            float v0 = pp2_W[(size_t)co * B1D + k] * s, v1 = pp2_W[(size_t)co * B1D + k + 1] * s;
            ((uint32_t*)g_W2th)[(size_t)(nb * 8 + c) * 4096 + r * 32 + (kp & 31)] = pack2hf(v0, v1);
            if (kp == 0) g_bias2[co] = pp2_b[co] * s + pp2_be[co];
        }
    } else if (bid < 768) {
        // m1: K=1152, ROWS=1024, KC=18
        for (int p = (bid - 256) * 256 + tid; p < 1024 * 576; p += 512 * 256) {
            int co = p / 576, kp = p % 576, k = kp * 2;
            int nb = co >> 7, r = co & 127, c = k >> 6;
            float s = BN_INV_F * m1_g[co];
            float v0 = m1_W[(size_t)co * KM1 + k] * s, v1 = m1_W[(size_t)co * KM1 + k + 1] * s;
            ((uint32_t*)g_M1th)[(size_t)(nb * 18 + c) * 4096 + r * 32 + (kp & 31)] = pack2hf(v0, v1);
            if (kp == 0) g_bm1[co] = m1_b[co] * s + m1_be[co];
        }
    } else if (bid < 832) {
        // m2: K=1024, ROWS=128, KC=16
        for (int p = (bid - 768) * 256 + tid; p < 128 * 512; p += 64 * 256) {
            int co = p >> 9, kp = p & 511, k = kp * 2;
            int r = co & 127, c = k >> 6;
            float s = BN_INV_F * m2_g[co];
            float v0 = m2_W[(size_t)co * M1D + k] * s, v1 = m2_W[(size_t)co * M1D + k + 1] * s;
            ((uint32_t*)g_M2th)[(size_t)c * 4096 + r * 32 + (kp & 31)] = pack2hf(v0, v1);
            if (kp == 0) g_bm2[co] = m2_b[co] * s + m2_be[co];
        }
    } else if (bid < 896) {
        for (int idx = (bid - 832) * 256 + tid; idx < 512 * 192; idx += 64 * 256) {
            int r = idx / 192, cc = idx % 192;
            g_LW[idx] = (cc < 64) ? Wih[r * 64 + cc] : Whh[r * 128 + cc - 64];
            if (cc == 0) g_Lb[r] = bih[r] + bhh[r];
        }
    } else if (bid < 898) {
        int k = (bid - 896) * 256 + tid;
        if (k < B1D) {
            float s1 = BN_INV_F * pp1_g[k];
            const float* row = pp1_W + (size_t)k * (ED + HD);
            float sa = 0.f, sb = 0.f, sc = 0.f;
            for (int e = 0; e < ED; e++) {
                float w = row[e];
                sa += w * sp_W[e * 2]; sb += w * sp_W[e * 2 + 1]; sc += w * sp_b[e];
            }
            g_A[k] = sa * s1; g_B[k] = sb * s1;
            g_bias1[k] = (pp1_b[k] + sc) * s1 + pp1_be[k];
            // fp16 tiles for hpre wmma: tile (nb*2 + c), r = col within 128, kk = h pair
            int nb = k >> 7, r = k & 127;
            for (int h = 0; h < HD; h += 2) {
                float w0 = row[ED + h] * s1, w1 = row[ED + h + 1] * s1;
                int c = h >> 6;
                ((uint32_t*)g_Wbth)[(size_t)(nb * 2 + c) * 4096 + r * 32 + ((h & 63) >> 1)] =
                    pack2hf(w0, w1);
            }
        }
    } else {
        for (int idx = (bid - 898) * 256 + tid; idx < NT * HD; idx += 126 * 256) {
            g_h[idx] = h0[idx]; g_c[idx] = c0[idx];
            if (idx < NT * 2) g_lp[idx] = last_pos[idx];
            if (idx < NT * ED) {
                int n = idx / ED, e = idx % ED;
                g_din[idx] = last_pos_rel[n * 2] * embW[e * 2] +
                             last_pos_rel[n * 2 + 1] * embW[e * 2 + 1] + embb[e];
            }
        }
    }
}

// ---------------- gates SIMT GEMM (K=192) ----------------
template <int FIRST>
__global__ __launch_bounds__(256) void gates_gemm() {
    int c0 = blockIdx.x * 128, grp = blockIdx.y, tid = threadIdx.x;
    int tx = tid & 31, ty = tid >> 5;
    __shared__ float a_s[32][64];
    __shared__ float w_s[64][129];
    int nbase = grp * 32;
    float acc[4][4] = {};
    for (int k0 = 0; k0 < 192; k0 += 64) {
        __syncthreads();
        for (int idx = tid; idx < 32 * 64; idx += 256) {
            int j = idx >> 6, k = idx & 63, kk = k0 + k;
            float v;
            if (kk < 64) v = g_din[(nbase + j) * ED + kk];
            else {
                int ped = nbase + j, cc = kk - 64;
                if (FIRST) v = g_h[ped * HD + cc];
                else {
                    float sum = g_hp[(size_t)ped * HD + cc]
                              + g_hp[(size_t)(NT + ped) * HD + cc]
                              + g_hp[(size_t)(2 * NT + ped) * HD + cc]
                              + g_hp[(size_t)(3 * NT + ped) * HD + cc];
                    v = fmaxf(sum + g_bm2[cc], 0.f);
                }
            }
            a_s[j][k] = v;
        }
        for (int idx = tid; idx < 128 * 64; idx += 256) {
            int c = idx >> 6, k = idx & 63;
            w_s[k][c] = g_LW[(size_t)(c0 + c) * 192 + k0 + k];
        }
        __syncthreads();
#pragma unroll 4
        for (int k = 0; k < 64; k++) {
            float xr[4], wr[4];
#pragma unroll
            for (int jj = 0; jj < 4; jj++) xr[jj] = a_s[ty + jj * 8][k];
#pragma unroll
            for (int cc = 0; cc < 4; cc++) wr[cc] = w_s[k][tx + cc * 32];
#pragma unroll
            for (int jj = 0; jj < 4; jj++)
#pragma unroll
                for (int cc = 0; cc < 4; cc++) acc[jj][cc] = fmaf(xr[jj], wr[cc], acc[jj][cc]);
        }
    }
#pragma unroll
    for (int jj = 0; jj < 4; jj++) {
        int n = nbase + ty + jj * 8;
#pragma unroll
        for (int cc = 0; cc < 4; cc++) {
            int c = c0 + tx + cc * 32;
            g_gates[(size_t)n * 512 + c] = acc[jj][cc] + g_Lb[c];
        }
    }
}

// ---------------- LSTM pointwise + h2 pack into m1 A-tiles ----------------
__global__ __launch_bounds__(128) void lstm_point(
    const float* __restrict__ posW, const float* __restrict__ posb,
    const float* __restrict__ embW, const float* __restrict__ embb,
    float* __restrict__ out_t) {
    int n = blockIdx.x, t = threadIdx.x;
    __shared__ float red0[HD], red1[HD], hs2[HD], rp[2];
    float gi = g_gates[n * 512 + 0 * HD + t];
    float gf = g_gates[n * 512 + 1 * HD + t];
    float gg = g_gates[n * 512 + 2 * HD + t];
    float go = g_gates[n * 512 + 3 * HD + t];
    float ig = 1.f / (1.f + expf(-gi));
    float fg = 1.f / (1.f + expf(-gf));
    float gv = tanhf(gg);
    float og = 1.f / (1.f + expf(-go));
    float c2 = fg * g_c[n * HD + t] + ig * gv;
    float h2 = og * tanhf(c2);
    g_c[n * HD + t] = c2;
    hs2[t] = h2;
    red0[t] = h2 * posW[t]; red1[t] = h2 * posW[HD + t];
    __syncthreads();
    for (int s = 64; s > 0; s >>= 1) {
        if (t < s) { red0[t] += red0[t + s]; red1[t] += red1[t + s]; }
        __syncthreads();
    }
    if (t < 2) {
        float v = ((t == 0) ? red0[0] : red1[0]) + posb[t];
        rp[t] = v;
        out_t[n * 2 + t] = v;
        g_lp[n * 2 + t] += v;
    }
    __syncthreads();
    if (t < ED) g_din[n * ED + t] = fmaf(rp[0], embW[t * 2], fmaf(rp[1], embW[t * 2 + 1], embb[t]));
    if (t < 64) {
        int mb = n >> 7, m = n & 127;
        int c = t >> 5;
        ((uint32_t*)g_mAh)[(size_t)(mb * 18 + c) * 4096 + m * 32 + (t & 31)] =
            pack2hf(hs2[2 * t], hs2[2 * t + 1]);
    }
}

// ---------------- hpre wmma: A = g_mAh chunks 0..1 (fp16 h2), W = g_Wbth ----------------
// grid(4 nbX, 8 mb), 256 thr; K=128 (2 k64 chunks), warp tile 32x64; single stage.
#define HP_SMEM 73728

__global__ __launch_bounds__(256, 2) void hpre_wmma() {
    extern __shared__ __align__(16) char smraw[];
    uint32_t base = smem_u32(smraw);
    float* c_s = (float*)smraw;
    int tid = threadIdx.x, w = tid >> 5;
    int wr = w >> 1, wc = w & 1;
    int nbX = blockIdx.x, mb = blockIdx.y;

    // stage all 4 tiles (A0, A1, W0, W1), padded rows (72 halves)
    for (int c = 0; c < 2; c++) {
        const __half* At = g_mAh + (size_t)(mb * 18 + c) * 8192;
        const __half* Wt = g_Wbth + (size_t)(nbX * 2 + c) * 8192;
        uint32_t sbA = base + c * 18432;
        uint32_t sbW = base + 36864 + c * 18432;
#pragma unroll
        for (int q = 0; q < 4; q++) {
            int i = tid + q * 256;
            int r = i >> 3, seg = i & 7;
            cpa(sbA + r * 144 + seg * 16, At + r * 64 + seg * 8);
            cpa(sbW + r * 144 + seg * 16, Wt + r * 64 + seg * 8);
        }
    }
    CPA_COMMIT();
    CPA_WAIT0();
    __syncthreads();

    wmma::fragment<wmma::accumulator, 16, 16, 16, float> acc[2][4];
#pragma unroll
    for (int mf = 0; mf < 2; mf++)
#pragma unroll
        for (int nf = 0; nf < 4; nf++) wmma::fill_fragment(acc[mf][nf], 0.f);

#pragma unroll
    for (int c = 0; c < 2; c++) {
        const __half* sA = (const __half*)(smraw + c * 18432);
        const __half* sW = (const __half*)(smraw + 36864 + c * 18432);
#pragma unroll
        for (int ks = 0; ks < 4; ks++) {
            wmma::fragment<wmma::matrix_a, 16, 16, 16, __half, wmma::row_major> af[2];
#pragma unroll
            for (int mf = 0; mf < 2; mf++)
                wmma::load_matrix_sync(af[mf], sA + (wr * 32 + mf * 16) * 72 + ks * 16, 72);
#pragma unroll
            for (int nf = 0; nf < 4; nf++) {
                wmma::fragment<wmma::matrix_b, 16, 16, 16, __half, wmma::col_major> bh;
                wmma::load_matrix_sync(bh, sW + (wc * 64 + nf * 16) * 72 + ks * 16, 72);
#pragma unroll
                for (int mf = 0; mf < 2; mf++)
                    wmma::mma_sync(acc[mf][nf], af[mf], bh, acc[mf][nf]);
            }
        }
    }
    __syncthreads();
#pragma unroll
    for (int mf = 0; mf < 2; mf++)
#pragma unroll
        for (int nf = 0; nf < 4; nf++)
            wmma::store_matrix_sync(c_s + (wr * 32 + mf * 16) * 136 + wc * 64 + nf * 16,
                                    acc[mf][nf], 136, wmma::mem_row_major);
    __syncthreads();
    for (int p = tid; p < 16384; p += 256) {
        int r = p >> 7, cc = p & 127;
        int col = nbX * 128 + cc;
        g_hpre[(size_t)(mb * 128 + r) * B1D + col] = c_s[r * 136 + cc] + g_bias1[col];
    }
}

// ---------------- build x1 fp16 tiles (once per step) ----------------
__global__ __launch_bounds__(256) void build_x1() {
    int c = blockIdx.x, ib = blockIdx.y, s = blockIdx.z;
    int tid = threadIdx.x;
    __shared__ float rxs[128], rys[128];
    if (tid < 128) {
        int i = ib * 4 + (tid >> 5), j = tid & 31;
        float dx = g_lp[(s * 32 + j) * 2]     - g_lp[(s * 32 + i) * 2];
        float dy = g_lp[(s * 32 + j) * 2 + 1] - g_lp[(s * 32 + i) * 2 + 1];
        float nrm = fmaxf(sqrtf(dx * dx + dy * dy), 1e-12f);
        rxs[tid] = dx / nrm; rys[tid] = dy / nrm;
    }
    __syncthreads();
    int grp = s * 8 + ib;
    uint32_t* oh = (uint32_t*)g_x1h + (size_t)(grp * 8 + c) * 4096;
    int kp = tid & 31, k = c * 64 + kp * 2;
    float2 ab0 = *(const float2*)(g_A + k);
    float2 bb0 = *(const float2*)(g_B + k);
#pragma unroll
    for (int q = 0; q < 16; q++) {
        int m = (tid >> 5) + q * 8;
        int pj = s * 32 + (m & 31);
        float rx = rxs[m], ry = rys[m];
        float2 hp = *(const float2*)(g_hpre + (size_t)pj * B1D + k);
        float v0 = fmaxf(hp.x + rx * ab0.x + ry * bb0.x, 0.f);
        float v1 = fmaxf(hp.y + rx * ab0.y + ry * bb0.y, 0.f);
        oh[m * 32 + kp] = pack2hf(v0, v1);
    }
}

// ---------------- pool wmma: k=64 chunks (KC=8), 2-stage, 2 CTAs/SM ----------------
#define POOL_SS 36864
#define POOL_SMEM 73728

__global__ __launch_bounds__(256, 2) void pool_gemm() {
    extern __shared__ __align__(16) char smraw[];
    uint32_t base = smem_u32(smraw);
    float* c_s = (float*)smraw;
    int tid = threadIdx.x, w = tid >> 5;
    int wr = w >> 1, wc = w & 1;
    int nbX = blockIdx.x, grpY = blockIdx.y;

    auto stage = [&](int buf, int c) {
        uint32_t sb = base + buf * POOL_SS;
        const __half* At = g_x1h + (size_t)(grpY * 8 + c) * 8192;
        const __half* Wt = g_W2th + (size_t)(nbX * 8 + c) * 8192;
#pragma unroll
        for (int q = 0; q < 4; q++) {
            int i = tid + q * 256;
            int r = i >> 3, seg = i & 7;
            cpa(sb + r * 144 + seg * 16, At + r * 64 + seg * 8);
            cpa(sb + 18432 + r * 144 + seg * 16, Wt + r * 64 + seg * 8);
        }
        CPA_COMMIT();
    };

    wmma::fragment<wmma::accumulator, 16, 16, 16, float> acc[2][4];
#pragma unroll
    for (int mf = 0; mf < 2; mf++)
#pragma unroll
        for (int nf = 0; nf < 4; nf++) wmma::fill_fragment(acc[mf][nf], 0.f);

    stage(0, 0);
    for (int c = 0; c < 8; c++) {
        if (c + 1 < 8) { stage((c + 1) & 1, c + 1); CPA_WAIT1(); } else { CPA_WAIT0(); }
        __syncthreads();
        const __half* sbuf = (const __half*)(smraw + (c & 1) * POOL_SS);
        const __half* whp = sbuf + 9216;
#pragma unroll
        for (int ks = 0; ks < 4; ks++) {
            wmma::fragment<wmma::matrix_a, 16, 16, 16, __half, wmma::row_major> af[2];
#pragma unroll
            for (int mf = 0; mf < 2; mf++)
                wmma::load_matrix_sync(af[mf], sbuf + (wr * 32 + mf * 16) * 72 + ks * 16, 72);
#pragma unroll
            for (int nf = 0; nf < 4; nf++) {
                wmma::fragment<wmma::matrix_b, 16, 16, 16, __half, wmma::col_major> bh;
                wmma::load_matrix_sync(bh, whp + (wc * 64 + nf * 16) * 72 + ks * 16, 72);
#pragma unroll
                for (int mf = 0; mf < 2; mf++)
                    wmma::mma_sync(acc[mf][nf], af[mf], bh, acc[mf][nf]);
            }
        }
        __syncthreads();
    }

    __syncthreads();
#pragma unroll
    for (int mf = 0; mf < 2; mf++)
#pragma unroll
        for (int nf = 0; nf < 4; nf++)
            wmma::store_matrix_sync(c_s + (wr * 32 + mf * 16) * 136 + wc * 64 + nf * 16,
                                    acc[mf][nf], 136, wmma::mem_row_major);
    __syncthreads();

    int s = grpY >> 3, ib = grpY & 7;
    {
        int il = tid >> 6, kp0 = tid & 63;
        int cc0 = kp0 * 2;
        float m0 = c_s[(il * 32) * 136 + cc0];
        float m1v = c_s[(il * 32) * 136 + cc0 + 1];
#pragma unroll 8
        for (int r = 1; r < 32; r++) {
            m0  = fmaxf(m0,  c_s[(il * 32 + r) * 136 + cc0]);
            m1v = fmaxf(m1v, c_s[(il * 32 + r) * 136 + cc0 + 1]);
        }
        int col = nbX * 128 + cc0;
        float v0 = fmaxf(m0 + g_bias2[col], 0.f);
        float v1 = fmaxf(m1v + g_bias2[col + 1], 0.f);
        int ped = s * 32 + ib * 4 + il;
        int mb = ped >> 7, m = ped & 127;
        int cch = 2 + nbX * 2 + (kp0 >> 5);
        ((uint32_t*)g_mAh)[(size_t)(mb * 18 + cch) * 4096 + m * 32 + (kp0 & 31)] =
            pack2hf(v0, v1);
    }
}

// ---------------- m1 / m2 wmma ----------------
template <int GM>
__global__ __launch_bounds__(256, 2) void wmma_gemm() {
    constexpr int KC = (GM == 1) ? 36 : 8;
    constexpr int ROWS = (GM == 1) ? 64 : 128;
    constexpr int NF = (GM == 1) ? 2 : 4;
    constexpr int WC = (GM == 1) ? 4 : 2;
    constexpr int SA = ROWS * 80;
    constexpr int SS = SA + 10240;
    extern __shared__ __align__(16) char smraw[];
    uint32_t base = smem_u32(smraw);
    float* c_s = (float*)smraw;

    int tid = threadIdx.x, w = tid >> 5;
    int wr = w / WC, wc = w % WC;
    int nbX = blockIdx.x, grpY = blockIdx.y;

    const __half* Ah_g = (GM == 1) ? g_mAh : g_mBh;
    const __half* Wh_g = (GM == 1) ? g_M1th : g_M2th;

    auto stage = [&](int buf, int c) {
        int tile0, sub, roff = 0, wtile;
        if (GM == 1) {
            int ch = c >> 1; sub = c & 1;
            tile0 = (grpY >> 1) * 18 + ch; roff = (grpY & 1) * 64;
            wtile = nbX * 18 + ch;
        } else {
            int gch = nbX * 8 + c; sub = gch & 1;
            tile0 = grpY * 16 + (gch >> 1);
            wtile = gch >> 1;
        }
        uint32_t sb = base + buf * SS;
        for (int i = tid; i < ROWS * 4; i += 256) {
            int r = i >> 2, seg = i & 3;
            size_t so = (size_t)tile0 * 8192 + (roff + r) * 64 + sub * 32 + seg * 8;
            cpa(sb + r * 80 + seg * 16, Ah_g + so);
        }
        for (int i = tid; i < 512; i += 256) {
            int r = i >> 2, seg = i & 3;
            size_t so = (size_t)wtile * 8192 + r * 64 + sub * 32 + seg * 8;
            cpa(sb + SA + r * 80 + seg * 16, Wh_g + so);
        }
        CPA_COMMIT();
    };

    wmma::fragment<wmma::accumulator, 16, 16, 16, float> acc[2][NF];
#pragma unroll
    for (int mf = 0; mf < 2; mf++)
#pragma unroll
        for (int nf = 0; nf < NF; nf++) wmma::fill_fragment(acc[mf][nf], 0.f);

    stage(0, 0);
    for (int c = 0; c < KC; c++) {
        if (c + 1 < KC) { stage((c + 1) & 1, c + 1); CPA_WAIT1(); } else { CPA_WAIT0(); }
        __syncthreads();
        const __half* sbuf = (const __half*)(smraw + (c & 1) * SS);
        const __half* whp = sbuf + SA / 2;
#pragma unroll
        for (int ks = 0; ks < 2; ks++) {
            wmma::fragment<wmma::matrix_a, 16, 16, 16, __half, wmma::row_major> af[2];
#pragma unroll
            for (int mf = 0; mf < 2; mf++)
                wmma::load_matrix_sync(af[mf], sbuf + (wr * 32 + mf * 16) * 40 + ks * 16, 40);
#pragma unroll
            for (int nf = 0; nf < NF; nf++) {
                wmma::fragment<wmma::matrix_b, 16, 16, 16, __half, wmma::col_major> bh;
                int coff = (wc * NF * 16 + nf * 16) * 40 + ks * 16;
                wmma::load_matrix_sync(bh, whp + coff, 40);
#pragma unroll
                for (int mf = 0; mf < 2; mf++)
                    wmma::mma_sync(acc[mf][nf], af[mf], bh, acc[mf][nf]);
            }
        }
        __syncthreads();
    }

    __syncthreads();
#pragma unroll
    for (int mf = 0; mf < 2; mf++)
#pragma unroll
        for (int nf = 0; nf < NF; nf++)
            wmma::store_matrix_sync(c_s + (wr * 32 + mf * 16) * 136 + wc * NF * 16 + nf * 16,
                                    acc[mf][nf], 136, wmma::mem_row_major);
    __syncthreads();

    if (GM == 1) {
        for (int p = tid; p < 4096; p += 256) {
            int r = p >> 6, kp = p & 63;
            int cc0 = kp * 2, col = nbX * 128 + cc0;
            float v0 = fmaxf(c_s[r * 136 + cc0]     + g_bm1[col], 0.f);
            float v1 = fmaxf(c_s[r * 136 + cc0 + 1] + g_bm1[col + 1], 0.f);
            int ped = grpY * 64 + r;
            int mb = ped >> 7, m = ped & 127;
            int cch = nbX * 2 + (kp >> 5);
            ((uint32_t*)g_mBh)[(size_t)(mb * 16 + cch) * 4096 + m * 32 + (kp & 31)] =
                pack2hf(v0, v1);
        }
    } else {
        float* dst = g_hp + (size_t)nbX * NT * HD + (size_t)grpY * 128 * HD;
        for (int p = tid; p < 16384; p += 256) {
            int r = p >> 7, cc = p & 127;
            dst[r * HD + cc] = c_s[r * 136 + cc];
        }
    }
}

// ---------------- host launch ----------------
extern "C" void kernel_launch(void* const* d_in, const int* in_sizes, int n_in,
                              void* d_out, int out_size) {
    const float* last_pos     = (const float*)d_in[0];
    const float* last_pos_rel = (const float*)d_in[1];
    const float* h0  = (const float*)d_in[2];
    const float* c0  = (const float*)d_in[3];
    const float* emb_W = (const float*)d_in[5];
    const float* emb_b = (const float*)d_in[6];
    const float* Wih = (const float*)d_in[7];
    const float* Whh = (const float*)d_in[8];
    const float* bih = (const float*)d_in[9];
    const float* bhh = (const float*)d_in[10];
    const float* pos_W = (const float*)d_in[11];
    const float* pos_b = (const float*)d_in[12];
    const float* sp_W = (const float*)d_in[13];
    const float* sp_b = (const float*)d_in[14];
    const float* pp1_W = (const float*)d_in[15];
    const float* pp1_b = (const float*)d_in[16];
    const float* pp1_g = (const float*)d_in[17];
    const float* pp1_be = (const float*)d_in[18];
    const float* pp2_W = (const float*)d_in[19];
    const float* pp2_b = (const float*)d_in[20];
    const float* pp2_g = (const float*)d_in[21];
    const float* pp2_be = (const float*)d_in[22];
    const float* m1_W = (const float*)d_in[23];
    const float* m1_b = (const float*)d_in[24];
    const float* m1_g = (const float*)d_in[25];
    const float* m1_be = (const float*)d_in[26];
    const float* m2_W = (const float*)d_in[27];
    const float* m2_b = (const float*)d_in[28];
    const float* m2_g = (const float*)d_in[29];
    const float* m2_be = (const float*)d_in[30];
    float* out = (float*)d_out;

    cudaFuncSetAttribute(hpre_wmma, cudaFuncAttributeMaxDynamicSharedMemorySize, HP_SMEM);
    cudaFuncSetAttribute(pool_gemm, cudaFuncAttributeMaxDynamicSharedMemorySize, POOL_SMEM);
    cudaFuncSetAttribute(wmma_gemm<1>, cudaFuncAttributeMaxDynamicSharedMemorySize, 36864);
    cudaFuncSetAttribute(wmma_gemm<2>, cudaFuncAttributeMaxDynamicSharedMemorySize, 69632);

    prep_all<<<1024, 256>>>(h0, c0, last_pos, last_pos_rel, emb_W, emb_b,
                            Wih, Whh, bih, bhh, sp_W, sp_b,
                            pp1_W, pp1_b, pp1_g, pp1_be,
                            pp2_W, pp2_b, pp2_g, pp2_be,
                            m1_W, m1_b, m1_g, m1_be,
                            m2_W, m2_b, m2_g, m2_be);

    for (int t = 0; t < TS; t++) {
        if (t == 0) gates_gemm<1><<<dim3(4, NT / 32), 256>>>();
        else        gates_gemm<0><<<dim3(4, NT / 32), 256>>>();
        lstm_point<<<NT, 128>>>(pos_W, pos_b, emb_W, emb_b, out + (size_t)t * NT * 2);
        hpre_wmma<<<dim3(4, 8), 256, HP_SMEM>>>();                 // hpre on tensor pipe
        build_x1<<<dim3(8, 8, SC), 256>>>();                       // x1 fp16 tiles
        pool_gemm<<<dim3(8, 256), 256, POOL_SMEM>>>();             // pool
        wmma_gemm<1><<<dim3(8, 16), 256, 36864>>>();               // m1
        wmma_gemm<2><<<dim3(4, 8), 256, 69632>>>();                // m2 split-K partials
    }
    (void)in_sizes; (void)n_in; (void)out_size;
}

// round 16
// speedup vs baseline: 1.3387x; 1.0824x over previous
#include <cuda_runtime.h>
#include <cuda_fp16.h>
#include <mma.h>
#include <stdint.h>
#include <math.h>

using namespace nvcuda;

#define NT 1024
#define HD 128
#define ED 64
#define SC 32
#define PP 32
#define B1D 512
#define B2D 1024
#define M1D 1024
#define TS 12
#define KM1 (HD + B2D)   // 1152
#define BN_INV_F 0.9999950000374997f

// ---------------- device state / scratch ----------------
static __device__ float g_c[NT * HD];
static __device__ float g_lp[NT * 2];
static __device__ float g_hpre[NT * B1D];
static __device__ float g_gates[NT * 4 * HD];
static __device__ float g_hp[4 * NT * HD];     // m2 split-K partials
// folded scalar weights
static __device__ float g_A[B1D], g_B[B1D], g_bias1[B1D];
static __device__ float g_bias2[B2D], g_bm1[M1D], g_bm2[HD];
static __device__ float g_Lb[4 * HD];
// pre-tiled fp16 weights: [nb][chunk64][128r x 64k] tiles (8192 halfs)
static __device__ __half g_W2th[8 * 8 * 8192];
static __device__ __half g_M1th[8 * 18 * 8192];
static __device__ __half g_M2th[16 * 8192];
static __device__ __half g_Wbth[4 * 2 * 8192];    // hpre weights
static __device__ __half g_LWth[4 * 3 * 8192];    // gates weights (K=192, 3 chunks)
// activation tiles, fp16, [group][chunk64][128x64]
static __device__ __half g_x1h[256 * 8 * 8192];   // pool A
static __device__ __half g_mAh[8 * 18 * 8192];    // m1 A (chunks 0..1 = h2 -> also hpre A)
static __device__ __half g_mBh[8 * 16 * 8192];    // m2 A
static __device__ __half g_gAh[8 * 3 * 8192];     // gates A: [din | h | h]

// ---------------- helpers ----------------
__device__ __forceinline__ uint32_t pack2hf(float v0, float v1) {
    __half2 h = __floats2half2_rn(v0, v1);
    return *(uint32_t*)&h;
}
__device__ __forceinline__ uint32_t smem_u32(const void* p) {
    uint32_t a;
    asm("{ .reg .u64 t; cvta.to.shared.u64 t, %1; cvt.u32.u64 %0, t; }" : "=r"(a) : "l"(p));
    return a;
}
__device__ __forceinline__ void cpa(uint32_t dsmem, const void* gsrc) {
    asm volatile("cp.async.cg.shared.global [%0], [%1], 16;" :: "r"(dsmem), "l"(gsrc) : "memory");
}
#define CPA_COMMIT() asm volatile("cp.async.commit_group;" ::: "memory")
#define CPA_WAIT1()  asm volatile("cp.async.wait_group 1;" ::: "memory")
#define CPA_WAIT0()  asm volatile("cp.async.wait_group 0;" ::: "memory")

// ---------------- consolidated prep (single launch) ----------------
__global__ __launch_bounds__(256) void prep_all(
    const float* __restrict__ h0, const float* __restrict__ c0,
    const float* __restrict__ last_pos, const float* __restrict__ last_pos_rel,
    const float* __restrict__ embW, const float* __restrict__ embb,
    const float* __restrict__ Wih, const float* __restrict__ Whh,
    const float* __restrict__ bih, const float* __restrict__ bhh,
    const float* __restrict__ sp_W, const float* __restrict__ sp_b,
    const float* __restrict__ pp1_W, const float* __restrict__ pp1_b,
    const float* __restrict__ pp1_g, const float* __restrict__ pp1_be,
    const float* __restrict__ pp2_W, const float* __restrict__ pp2_b,
    const float* __restrict__ pp2_g, const float* __restrict__ pp2_be,
    const float* __restrict__ m1_W, const float* __restrict__ m1_b,
    const float* __restrict__ m1_g, const float* __restrict__ m1_be,
    const float* __restrict__ m2_W, const float* __restrict__ m2_b,
    const float* __restrict__ m2_g, const float* __restrict__ m2_be) {
    int bid = blockIdx.x, tid = threadIdx.x;
    if (bid < 256) {
        // W2: K=512, ROWS=1024, KC=8
        for (int p = bid * 256 + tid; p < 1024 * 256; p += 256 * 256) {
            int co = p >> 8, kp = p & 255, k = kp * 2;
            int nb = co >> 7, r = co & 127, c = k >> 6;
            float s = BN_INV_F * pp2_g[co];
            float v0 = pp2_W[(size_t)co * B1D + k] * s, v1 = pp2_W[(size_t)co * B1D + k + 1] * s;
            ((uint32_t*)g_W2th)[(size_t)(nb * 8 + c) * 4096 + r * 32 + (kp & 31)] = pack2hf(v0, v1);
            if (kp == 0) g_bias2[co] = pp2_b[co] * s + pp2_be[co];
        }
    } else if (bid < 768) {
        // m1: K=1152, ROWS=1024, KC=18
        for (int p = (bid - 256) * 256 + tid; p < 1024 * 576; p += 512 * 256) {
            int co = p / 576, kp = p % 576, k = kp * 2;
            int nb = co >> 7, r = co & 127, c = k >> 6;
            float s = BN_INV_F * m1_g[co];
            float v0 = m1_W[(size_t)co * KM1 + k] * s, v1 = m1_W[(size_t)co * KM1 + k + 1] * s;
            ((uint32_t*)g_M1th)[(size_t)(nb * 18 + c) * 4096 + r * 32 + (kp & 31)] = pack2hf(v0, v1);
            if (kp == 0) g_bm1[co] = m1_b[co] * s + m1_be[co];
        }
    } else if (bid < 832) {
        // m2: K=1024, ROWS=128, KC=16
        for (int p = (bid - 768) * 256 + tid; p < 128 * 512; p += 64 * 256) {
            int co = p >> 9, kp = p & 511, k = kp * 2;
            int r = co & 127, c = k >> 6;
            float s = BN_INV_F * m2_g[co];
            float v0 = m2_W[(size_t)co * M1D + k] * s, v1 = m2_W[(size_t)co * M1D + k + 1] * s;
            ((uint32_t*)g_M2th)[(size_t)c * 4096 + r * 32 + (kp & 31)] = pack2hf(v0, v1);
            if (kp == 0) g_bm2[co] = m2_b[co] * s + m2_be[co];
        }
    } else if (bid < 896) {
        // LW fp16 tiles: 512 rows x 96 kpairs
        for (int p = (bid - 832) * 256 + tid; p < 512 * 96; p += 64 * 256) {
            int r = p / 96, kp = p % 96, k = kp * 2;
            float v0 = (k < 64) ? Wih[r * 64 + k] : Whh[r * 128 + k - 64];
            float v1 = (k + 1 < 64) ? Wih[r * 64 + k + 1] : Whh[r * 128 + k + 1 - 64];
            int nb = r >> 7, rr = r & 127, kc = kp >> 5;
            ((uint32_t*)g_LWth)[(size_t)(nb * 3 + kc) * 4096 + rr * 32 + (kp & 31)] = pack2hf(v0, v1);
            if (kp == 0) g_Lb[r] = bih[r] + bhh[r];
        }
    } else if (bid < 898) {
        int k = (bid - 896) * 256 + tid;
        if (k < B1D) {
            float s1 = BN_INV_F * pp1_g[k];
            const float* row = pp1_W + (size_t)k * (ED + HD);
            float sa = 0.f, sb = 0.f, sc = 0.f;
            for (int e = 0; e < ED; e++) {
                float w = row[e];
                sa += w * sp_W[e * 2]; sb += w * sp_W[e * 2 + 1]; sc += w * sp_b[e];
            }
            g_A[k] = sa * s1; g_B[k] = sb * s1;
            g_bias1[k] = (pp1_b[k] + sc) * s1 + pp1_be[k];
            int nb = k >> 7, r = k & 127;
            for (int h = 0; h < HD; h += 2) {
                float w0 = row[ED + h] * s1, w1 = row[ED + h + 1] * s1;
                int c = h >> 6;
                ((uint32_t*)g_Wbth)[(size_t)(nb * 2 + c) * 4096 + r * 32 + ((h & 63) >> 1)] =
                    pack2hf(w0, w1);
            }
        }
    } else {
        for (int idx = (bid - 898) * 256 + tid; idx < NT * HD; idx += 126 * 256) {
            g_c[idx] = c0[idx];
            if (idx < NT * 2) g_lp[idx] = last_pos[idx];
            if ((idx & 1) == 0) {
                // h0 -> gates A chunks 1..2
                int ped = idx >> 7, h = idx & 127;
                int mb = ped >> 7, m = ped & 127;
                int ch = 1 + (h >> 6), kk = (h & 63) >> 1;
                ((uint32_t*)g_gAh)[(size_t)(mb * 3 + ch) * 4096 + m * 32 + kk] =
                    pack2hf(h0[idx], h0[idx + 1]);
            }
            if (idx < NT * ED && (idx & 1) == 0) {
                // din0 -> gates A chunk 0
                int n = idx >> 6, e = idx & 63;
                float lx = last_pos_rel[n * 2], ly = last_pos_rel[n * 2 + 1];
                float v0 = lx * embW[e * 2]       + ly * embW[e * 2 + 1]       + embb[e];
                float v1 = lx * embW[(e + 1) * 2] + ly * embW[(e + 1) * 2 + 1] + embb[e + 1];
                int mb = n >> 7, m = n & 127;
                ((uint32_t*)g_gAh)[(size_t)(mb * 3) * 4096 + m * 32 + (e >> 1)] = pack2hf(v0, v1);
            }
        }
    }
}

// ---------------- combine m2 partials -> h fp16 into gates A chunks 1..2 ----------------
__global__ __launch_bounds__(256) void combine_h() {
    for (int p = blockIdx.x * 256 + threadIdx.x; p < NT * 64; p += gridDim.x * 256) {
        int ped = p >> 6, kp = p & 63, cc = kp * 2;
        float s0 = g_hp[(size_t)ped * HD + cc]
                 + g_hp[(size_t)(NT + ped) * HD + cc]
                 + g_hp[(size_t)(2 * NT + ped) * HD + cc]
                 + g_hp[(size_t)(3 * NT + ped) * HD + cc];
        float s1 = g_hp[(size_t)ped * HD + cc + 1]
                 + g_hp[(size_t)(NT + ped) * HD + cc + 1]
                 + g_hp[(size_t)(2 * NT + ped) * HD + cc + 1]
                 + g_hp[(size_t)(3 * NT + ped) * HD + cc + 1];
        float v0 = fmaxf(s0 + g_bm2[cc], 0.f);
        float v1 = fmaxf(s1 + g_bm2[cc + 1], 0.f);
        int mb = ped >> 7, m = ped & 127;
        int ch = 1 + (cc >> 6);
        ((uint32_t*)g_gAh)[(size_t)(mb * 3 + ch) * 4096 + m * 32 + (kp & 31)] = pack2hf(v0, v1);
    }
}

// ---------------- gates wmma: A = g_gAh (3 chunks), W = g_LWth ----------------
// grid(4 nbX, 8 mb), 256 thr; K=192 (3 k64 chunks), warp tile 32x64; single stage.
#define GA_SMEM 110592

__global__ __launch_bounds__(256) void gates_wmma() {
    extern __shared__ __align__(16) char smraw[];
    uint32_t base = smem_u32(smraw);
    float* c_s = (float*)smraw;
    int tid = threadIdx.x, w = tid >> 5;
    int wr = w >> 1, wc = w & 1;
    int nbX = blockIdx.x, mb = blockIdx.y;

    for (int c = 0; c < 3; c++) {
        const __half* At = g_gAh + (size_t)(mb * 3 + c) * 8192;
        const __half* Wt = g_LWth + (size_t)(nbX * 3 + c) * 8192;
        uint32_t sbA = base + c * 18432;
        uint32_t sbW = base + 55296 + c * 18432;
#pragma unroll
        for (int q = 0; q < 4; q++) {
            int i = tid + q * 256;
            int r = i >> 3, seg = i & 7;
            cpa(sbA + r * 144 + seg * 16, At + r * 64 + seg * 8);
            cpa(sbW + r * 144 + seg * 16, Wt + r * 64 + seg * 8);
        }
    }
    CPA_COMMIT();
    CPA_WAIT0();
    __syncthreads();

    wmma::fragment<wmma::accumulator, 16, 16, 16, float> acc[2][4];
#pragma unroll
    for (int mf = 0; mf < 2; mf++)
#pragma unroll
        for (int nf = 0; nf < 4; nf++) wmma::fill_fragment(acc[mf][nf], 0.f);

#pragma unroll
    for (int c = 0; c < 3; c++) {
        const __half* sA = (const __half*)(smraw + c * 18432);
        const __half* sW = (const __half*)(smraw + 55296 + c * 18432);
#pragma unroll
        for (int ks = 0; ks < 4; ks++) {
            wmma::fragment<wmma::matrix_a, 16, 16, 16, __half, wmma::row_major> af[2];
#pragma unroll
            for (int mf = 0; mf < 2; mf++)
                wmma::load_matrix_sync(af[mf], sA + (wr * 32 + mf * 16) * 72 + ks * 16, 72);
#pragma unroll
            for (int nf = 0; nf < 4; nf++) {
                wmma::fragment<wmma::matrix_b, 16, 16, 16, __half, wmma::col_major> bh;
                wmma::load_matrix_sync(bh, sW + (wc * 64 + nf * 16) * 72 + ks * 16, 72);
#pragma unroll
                for (int mf = 0; mf < 2; mf++)
                    wmma::mma_sync(acc[mf][nf], af[mf], bh, acc[mf][nf]);
            }
        }
    }
    __syncthreads();
#pragma unroll
    for (int mf = 0; mf < 2; mf++)
#pragma unroll
        for (int nf = 0; nf < 4; nf++)
            wmma::store_matrix_sync(c_s + (wr * 32 + mf * 16) * 136 + wc * 64 + nf * 16,
                                    acc[mf][nf], 136, wmma::mem_row_major);
    __syncthreads();
    for (int p = tid; p < 16384; p += 256) {
        int r = p >> 7, cc = p & 127;
        int col = nbX * 128 + cc;
        g_gates[(size_t)(mb * 128 + r) * 512 + col] = c_s[r * 136 + cc] + g_Lb[col];
    }
}

// ---------------- LSTM pointwise + h2/din pack ----------------
__global__ __launch_bounds__(128) void lstm_point(
    const float* __restrict__ posW, const float* __restrict__ posb,
    const float* __restrict__ embW, const float* __restrict__ embb,
    float* __restrict__ out_t) {
    int n = blockIdx.x, t = threadIdx.x;
    __shared__ float red0[HD], red1[HD], hs2[HD], dsm[ED], rp[2];
    float gi = g_gates[n * 512 + 0 * HD + t];
    float gf = g_gates[n * 512 + 1 * HD + t];
    float gg = g_gates[n * 512 + 2 * HD + t];
    float go = g_gates[n * 512 + 3 * HD + t];
    float ig = 1.f / (1.f + expf(-gi));
    float fg = 1.f / (1.f + expf(-gf));
    float gv = tanhf(gg);
    float og = 1.f / (1.f + expf(-go));
    float c2 = fg * g_c[n * HD + t] + ig * gv;
    float h2 = og * tanhf(c2);
    g_c[n * HD + t] = c2;
    hs2[t] = h2;
    red0[t] = h2 * posW[t]; red1[t] = h2 * posW[HD + t];
    __syncthreads();
    for (int s = 64; s > 0; s >>= 1) {
        if (t < s) { red0[t] += red0[t + s]; red1[t] += red1[t + s]; }
        __syncthreads();
    }
    if (t < 2) {
        float v = ((t == 0) ? red0[0] : red1[0]) + posb[t];
        rp[t] = v;
        out_t[n * 2 + t] = v;
        g_lp[n * 2 + t] += v;
    }
    __syncthreads();
    if (t < ED) dsm[t] = fmaf(rp[0], embW[t * 2], fmaf(rp[1], embW[t * 2 + 1], embb[t]));
    __syncthreads();
    int mb = n >> 7, m = n & 127;
    if (t < 64) {
        // h2 pairs -> m1 A chunks 0..1 (also hpre A)
        int c = t >> 5;
        ((uint32_t*)g_mAh)[(size_t)(mb * 18 + c) * 4096 + m * 32 + (t & 31)] =
            pack2hf(hs2[2 * t], hs2[2 * t + 1]);
    }
    if (t < 32) {
        // din pairs -> gates A chunk 0
        ((uint32_t*)g_gAh)[(size_t)(mb * 3) * 4096 + m * 32 + t] =
            pack2hf(dsm[2 * t], dsm[2 * t + 1]);
    }
}

// ---------------- hpre wmma ----------------
#define HP_SMEM 73728

__global__ __launch_bounds__(256, 2) void hpre_wmma() {
    extern __shared__ __align__(16) char smraw[];
    uint32_t base = smem_u32(smraw);
    float* c_s = (float*)smraw;
    int tid = threadIdx.x, w = tid >> 5;
    int wr = w >> 1, wc = w & 1;
    int nbX = blockIdx.x, mb = blockIdx.y;

    for (int c = 0; c < 2; c++) {
        const __half* At = g_mAh + (size_t)(mb * 18 + c) * 8192;
        const __half* Wt = g_Wbth + (size_t)(nbX * 2 + c) * 8192;
        uint32_t sbA = base + c * 18432;
        uint32_t sbW = base + 36864 + c * 18432;
#pragma unroll
        for (int q = 0; q < 4; q++) {
            int i = tid + q * 256;
            int r = i >> 3, seg = i & 7;
            cpa(sbA + r * 144 + seg * 16, At + r * 64 + seg * 8);
            cpa(sbW + r * 144 + seg * 16, Wt + r * 64 + seg * 8);
        }
    }
    CPA_COMMIT();
    CPA_WAIT0();
    __syncthreads();

    wmma::fragment<wmma::accumulator, 16, 16, 16, float> acc[2][4];
#pragma unroll
    for (int mf = 0; mf < 2; mf++)
#pragma unroll
        for (int nf = 0; nf < 4; nf++) wmma::fill_fragment(acc[mf][nf], 0.f);

#pragma unroll
    for (int c = 0; c < 2; c++) {
        const __half* sA = (const __half*)(smraw + c * 18432);
        const __half* sW = (const __half*)(smraw + 36864 + c * 18432);
#pragma unroll
        for (int ks = 0; ks < 4; ks++) {
            wmma::fragment<wmma::matrix_a, 16, 16, 16, __half, wmma::row_major> af[2];
#pragma unroll
            for (int mf = 0; mf < 2; mf++)
                wmma::load_matrix_sync(af[mf], sA + (wr * 32 + mf * 16) * 72 + ks * 16, 72);
#pragma unroll
            for (int nf = 0; nf < 4; nf++) {
                wmma::fragment<wmma::matrix_b, 16, 16, 16, __half, wmma::col_major> bh;
                wmma::load_matrix_sync(bh, sW + (wc * 64 + nf * 16) * 72 + ks * 16, 72);
#pragma unroll
                for (int mf = 0; mf < 2; mf++)
                    wmma::mma_sync(acc[mf][nf], af[mf], bh, acc[mf][nf]);
            }
        }
    }
    __syncthreads();
#pragma unroll
    for (int mf = 0; mf < 2; mf++)
#pragma unroll
        for (int nf = 0; nf < 4; nf++)
            wmma::store_matrix_sync(c_s + (wr * 32 + mf * 16) * 136 + wc * 64 + nf * 16,
                                    acc[mf][nf], 136, wmma::mem_row_major);
    __syncthreads();
    for (int p = tid; p < 16384; p += 256) {
        int r = p >> 7, cc = p & 127;
        int col = nbX * 128 + cc;
        g_hpre[(size_t)(mb * 128 + r) * B1D + col] = c_s[r * 136 + cc] + g_bias1[col];
    }
}

// ---------------- build x1 fp16 tiles ----------------
__global__ __launch_bounds__(256) void build_x1() {
    int c = blockIdx.x, ib = blockIdx.y, s = blockIdx.z;
    int tid = threadIdx.x;
    __shared__ float rxs[128], rys[128];
    if (tid < 128) {
        int i = ib * 4 + (tid >> 5), j = tid & 31;
        float dx = g_lp[(s * 32 + j) * 2]     - g_lp[(s * 32 + i) * 2];
        float dy = g_lp[(s * 32 + j) * 2 + 1] - g_lp[(s * 32 + i) * 2 + 1];
        float nrm = fmaxf(sqrtf(dx * dx + dy * dy), 1e-12f);
        rxs[tid] = dx / nrm; rys[tid] = dy / nrm;
    }
    __syncthreads();
    int grp = s * 8 + ib;
    uint32_t* oh = (uint32_t*)g_x1h + (size_t)(grp * 8 + c) * 4096;
    int kp = tid & 31, k = c * 64 + kp * 2;
    float2 ab0 = *(const float2*)(g_A + k);
    float2 bb0 = *(const float2*)(g_B + k);
#pragma unroll
    for (int q = 0; q < 16; q++) {
        int m = (tid >> 5) + q * 8;
        int pj = s * 32 + (m & 31);
        float rx = rxs[m], ry = rys[m];
        float2 hp = *(const float2*)(g_hpre + (size_t)pj * B1D + k);
        float v0 = fmaxf(hp.x + rx * ab0.x + ry * bb0.x, 0.f);
        float v1 = fmaxf(hp.y + rx * ab0.y + ry * bb0.y, 0.f);
        oh[m * 32 + kp] = pack2hf(v0, v1);
    }
}

// ---------------- pool wmma: k=64 chunks (KC=8), 2-stage, 2 CTAs/SM ----------------
#define POOL_SS 36864
#define POOL_SMEM 73728

__global__ __launch_bounds__(256, 2) void pool_gemm() {
    extern __shared__ __align__(16) char smraw[];
    uint32_t base = smem_u32(smraw);
    float* c_s = (float*)smraw;
    int tid = threadIdx.x, w = tid >> 5;
    int wr = w >> 1, wc = w & 1;
    int nbX = blockIdx.x, grpY = blockIdx.y;

    auto stage = [&](int buf, int c) {
        uint32_t sb = base + buf * POOL_SS;
        const __half* At = g_x1h + (size_t)(grpY * 8 + c) * 8192;
        const __half* Wt = g_W2th + (size_t)(nbX * 8 + c) * 8192;
#pragma unroll
        for (int q = 0; q < 4; q++) {
            int i = tid + q * 256;
            int r = i >> 3, seg = i & 7;
            cpa(sb + r * 144 + seg * 16, At + r * 64 + seg * 8);
            cpa(sb + 18432 + r * 144 + seg * 16, Wt + r * 64 + seg * 8);
        }
        CPA_COMMIT();
    };

    wmma::fragment<wmma::accumulator, 16, 16, 16, float> acc[2][4];
#pragma unroll
    for (int mf = 0; mf < 2; mf++)
#pragma unroll
        for (int nf = 0; nf < 4; nf++) wmma::fill_fragment(acc[mf][nf], 0.f);

    stage(0, 0);
    for (int c = 0; c < 8; c++) {
        if (c + 1 < 8) { stage((c + 1) & 1, c + 1); CPA_WAIT1(); } else { CPA_WAIT0(); }
        __syncthreads();
        const __half* sbuf = (const __half*)(smraw + (c & 1) * POOL_SS);
        const __half* whp = sbuf + 9216;
#pragma unroll
        for (int ks = 0; ks < 4; ks++) {
            wmma::fragment<wmma::matrix_a, 16, 16, 16, __half, wmma::row_major> af[2];
#pragma unroll
            for (int mf = 0; mf < 2; mf++)
                wmma::load_matrix_sync(af[mf], sbuf + (wr * 32 + mf * 16) * 72 + ks * 16, 72);
#pragma unroll
            for (int nf = 0; nf < 4; nf++) {
                wmma::fragment<wmma::matrix_b, 16, 16, 16, __half, wmma::col_major> bh;
                wmma::load_matrix_sync(bh, whp + (wc * 64 + nf * 16) * 72 + ks * 16, 72);
#pragma unroll
                for (int mf = 0; mf < 2; mf++)
                    wmma::mma_sync(acc[mf][nf], af[mf], bh, acc[mf][nf]);
            }
        }
        __syncthreads();
    }

    __syncthreads();
#pragma unroll
    for (int mf = 0; mf < 2; mf++)
#pragma unroll
        for (int nf = 0; nf < 4; nf++)
            wmma::store_matrix_sync(c_s + (wr * 32 + mf * 16) * 136 + wc * 64 + nf * 16,
                                    acc[mf][nf], 136, wmma::mem_row_major);
    __syncthreads();

    int s = grpY >> 3, ib = grpY & 7;
    {
        int il = tid >> 6, kp0 = tid & 63;
        int cc0 = kp0 * 2;
        float m0 = c_s[(il * 32) * 136 + cc0];
        float m1v = c_s[(il * 32) * 136 + cc0 + 1];
#pragma unroll 8
        for (int r = 1; r < 32; r++) {
            m0  = fmaxf(m0,  c_s[(il * 32 + r) * 136 + cc0]);
            m1v = fmaxf(m1v, c_s[(il * 32 + r) * 136 + cc0 + 1]);
        }
        int col = nbX * 128 + cc0;
        float v0 = fmaxf(m0 + g_bias2[col], 0.f);
        float v1 = fmaxf(m1v + g_bias2[col + 1], 0.f);
        int ped = s * 32 + ib * 4 + il;
        int mb = ped >> 7, m = ped & 127;
        int cch = 2 + nbX * 2 + (kp0 >> 5);
        ((uint32_t*)g_mAh)[(size_t)(mb * 18 + cch) * 4096 + m * 32 + (kp0 & 31)] =
            pack2hf(v0, v1);
    }
}

// ---------------- m1 / m2 wmma ----------------
template <int GM>
__global__ __launch_bounds__(256, 2) void wmma_gemm() {
    constexpr int KC = (GM == 1) ? 36 : 8;
    constexpr int ROWS = (GM == 1) ? 64 : 128;
    constexpr int NF = (GM == 1) ? 2 : 4;
    constexpr int WC = (GM == 1) ? 4 : 2;
    constexpr int SA = ROWS * 80;
    constexpr int SS = SA + 10240;
    extern __shared__ __align__(16) char smraw[];
    uint32_t base = smem_u32(smraw);
    float* c_s = (float*)smraw;

    int tid = threadIdx.x, w = tid >> 5;
    int wr = w / WC, wc = w % WC;
    int nbX = blockIdx.x, grpY = blockIdx.y;

    const __half* Ah_g = (GM == 1) ? g_mAh : g_mBh;
    const __half* Wh_g = (GM == 1) ? g_M1th : g_M2th;

    auto stage = [&](int buf, int c) {
        int tile0, sub, roff = 0, wtile;
        if (GM == 1) {
            int ch = c >> 1; sub = c & 1;
            tile0 = (grpY >> 1) * 18 + ch; roff = (grpY & 1) * 64;
            wtile = nbX * 18 + ch;
        } else {
            int gch = nbX * 8 + c; sub = gch & 1;
            tile0 = grpY * 16 + (gch >> 1);
            wtile = gch >> 1;
        }
        uint32_t sb = base + buf * SS;
        for (int i = tid; i < ROWS * 4; i += 256) {
            int r = i >> 2, seg = i & 3;
            size_t so = (size_t)tile0 * 8192 + (roff + r) * 64 + sub * 32 + seg * 8;
            cpa(sb + r * 80 + seg * 16, Ah_g + so);
        }
        for (int i = tid; i < 512; i += 256) {
            int r = i >> 2, seg = i & 3;
            size_t so = (size_t)wtile * 8192 + r * 64 + sub * 32 + seg * 8;
            cpa(sb + SA + r * 80 + seg * 16, Wh_g + so);
        }
        CPA_COMMIT();
    };

    wmma::fragment<wmma::accumulator, 16, 16, 16, float> acc[2][NF];
#pragma unroll
    for (int mf = 0; mf < 2; mf++)
#pragma unroll
        for (int nf = 0; nf < NF; nf++) wmma::fill_fragment(acc[mf][nf], 0.f);

    stage(0, 0);
    for (int c = 0; c < KC; c++) {
        if (c + 1 < KC) { stage((c + 1) & 1, c + 1); CPA_WAIT1(); } else { CPA_WAIT0(); }
        __syncthreads();
        const __half* sbuf = (const __half*)(smraw + (c & 1) * SS);
        const __half* whp = sbuf + SA / 2;
#pragma unroll
        for (int ks = 0; ks < 2; ks++) {
            wmma::fragment<wmma::matrix_a, 16, 16, 16, __half, wmma::row_major> af[2];
#pragma unroll
            for (int mf = 0; mf < 2; mf++)
                wmma::load_matrix_sync(af[mf], sbuf + (wr * 32 + mf * 16) * 40 + ks * 16, 40);
#pragma unroll
            for (int nf = 0; nf < NF; nf++) {
                wmma::fragment<wmma::matrix_b, 16, 16, 16, __half, wmma::col_major> bh;
                int coff = (wc * NF * 16 + nf * 16) * 40 + ks * 16;
                wmma::load_matrix_sync(bh, whp + coff, 40);
#pragma unroll
                for (int mf = 0; mf < 2; mf++)
                    wmma::mma_sync(acc[mf][nf], af[mf], bh, acc[mf][nf]);
            }
        }
        __syncthreads();
    }

    __syncthreads();
#pragma unroll
    for (int mf = 0; mf < 2; mf++)
#pragma unroll
        for (int nf = 0; nf < NF; nf++)
            wmma::store_matrix_sync(c_s + (wr * 32 + mf * 16) * 136 + wc * NF * 16 + nf * 16,
                                    acc[mf][nf], 136, wmma::mem_row_major);
    __syncthreads();

    if (GM == 1) {
        for (int p = tid; p < 4096; p += 256) {
            int r = p >> 6, kp = p & 63;
            int cc0 = kp * 2, col = nbX * 128 + cc0;
            float v0 = fmaxf(c_s[r * 136 + cc0]     + g_bm1[col], 0.f);
            float v1 = fmaxf(c_s[r * 136 + cc0 + 1] + g_bm1[col + 1], 0.f);
            int ped = grpY * 64 + r;
            int mb = ped >> 7, m = ped & 127;
            int cch = nbX * 2 + (kp >> 5);
            ((uint32_t*)g_mBh)[(size_t)(mb * 16 + cch) * 4096 + m * 32 + (kp & 31)] =
                pack2hf(v0, v1);
        }
    } else {
        float* dst = g_hp + (size_t)nbX * NT * HD + (size_t)grpY * 128 * HD;
        for (int p = tid; p < 16384; p += 256) {
            int r = p >> 7, cc = p & 127;
            dst[r * HD + cc] = c_s[r * 136 + cc];
        }
    }
}

// ---------------- host launch ----------------
extern "C" void kernel_launch(void* const* d_in, const int* in_sizes, int n_in,
                              void* d_out, int out_size) {
    const float* last_pos     = (const float*)d_in[0];
    const float* last_pos_rel = (const float*)d_in[1];
    const float* h0  = (const float*)d_in[2];
    const float* c0  = (const float*)d_in[3];
    const float* emb_W = (const float*)d_in[5];
    const float* emb_b = (const float*)d_in[6];
    const float* Wih = (const float*)d_in[7];
    const float* Whh = (const float*)d_in[8];
    const float* bih = (const float*)d_in[9];
    const float* bhh = (const float*)d_in[10];
    const float* pos_W = (const float*)d_in[11];
    const float* pos_b = (const float*)d_in[12];
    const float* sp_W = (const float*)d_in[13];
    const float* sp_b = (const float*)d_in[14];
    const float* pp1_W = (const float*)d_in[15];
    const float* pp1_b = (const float*)d_in[16];
    const float* pp1_g = (const float*)d_in[17];
    const float* pp1_be = (const float*)d_in[18];
    const float* pp2_W = (const float*)d_in[19];
    const float* pp2_b = (const float*)d_in[20];
    const float* pp2_g = (const float*)d_in[21];
    const float* pp2_be = (const float*)d_in[22];
    const float* m1_W = (const float*)d_in[23];
    const float* m1_b = (const float*)d_in[24];
    const float* m1_g = (const float*)d_in[25];
    const float* m1_be = (const float*)d_in[26];
    const float* m2_W = (const float*)d_in[27];
    const float* m2_b = (const float*)d_in[28];
    const float* m2_g = (const float*)d_in[29];
    const float* m2_be = (const float*)d_in[30];
    float* out = (float*)d_out;

    cudaFuncSetAttribute(gates_wmma, cudaFuncAttributeMaxDynamicSharedMemorySize, GA_SMEM);
    cudaFuncSetAttribute(hpre_wmma, cudaFuncAttributeMaxDynamicSharedMemorySize, HP_SMEM);
    cudaFuncSetAttribute(pool_gemm, cudaFuncAttributeMaxDynamicSharedMemorySize, POOL_SMEM);
    cudaFuncSetAttribute(wmma_gemm<1>, cudaFuncAttributeMaxDynamicSharedMemorySize, 36864);
    cudaFuncSetAttribute(wmma_gemm<2>, cudaFuncAttributeMaxDynamicSharedMemorySize, 69632);

    prep_all<<<1024, 256>>>(h0, c0, last_pos, last_pos_rel, emb_W, emb_b,
                            Wih, Whh, bih, bhh, sp_W, sp_b,
                            pp1_W, pp1_b, pp1_g, pp1_be,
                            pp2_W, pp2_b, pp2_g, pp2_be,
                            m1_W, m1_b, m1_g, m1_be,
                            m2_W, m2_b, m2_g, m2_be);

    for (int t = 0; t < TS; t++) {
        gates_wmma<<<dim3(4, 8), 256, GA_SMEM>>>();
        lstm_point<<<NT, 128>>>(pos_W, pos_b, emb_W, emb_b, out + (size_t)t * NT * 2);
        hpre_wmma<<<dim3(4, 8), 256, HP_SMEM>>>();
        build_x1<<<dim3(8, 8, SC), 256>>>();
        pool_gemm<<<dim3(8, 256), 256, POOL_SMEM>>>();
        wmma_gemm<1><<<dim3(8, 16), 256, 36864>>>();
        wmma_gemm<2><<<dim3(4, 8), 256, 69632>>>();
        if (t + 1 < TS) combine_h<<<64, 256>>>();   // h(t+1) fp16 tiles for next gates
    }
    (void)in_sizes; (void)n_in; (void)out_size;
}